// round 5
// baseline (speedup 1.0000x reference)
#include <cuda_runtime.h>
#include <cuda_bf16.h>
#include <math.h>
#include <stdint.h>

#define T_   2048
#define B_   8
#define S_   512
#define D_   512
#define H_   8
#define DH   64
#define DFF_ 2048
#define NQ_  10
#define W_   16
#define NW   128
#define EPS  1e-5f
#define NEGV -1e30f

// ---------------- scratch (no dynamic allocation allowed) ----------------
__device__ float g_qn[NQ_ * D_];
__device__ float g_qa[B_ * NW * D_];
__device__ float g_x1[T_ * B_ * D_];
__device__ float g_q [T_ * B_ * D_];
__device__ float g_kv[S_ * B_ * 2 * D_];
__device__ float g_tmp[T_ * B_ * D_];
__device__ float g_x2[T_ * B_ * D_];

__device__ __nv_bfloat16 g_x1h[T_ * B_ * D_], g_x1l[T_ * B_ * D_];
__device__ __nv_bfloat16 g_x2h[T_ * B_ * D_], g_x2l[T_ * B_ * D_];
__device__ __nv_bfloat16 g_obh[T_ * B_ * D_], g_obl[T_ * B_ * D_];
__device__ __nv_bfloat16 g_hh [T_ * B_ * DFF_], g_hl [T_ * B_ * DFF_];
__device__ __nv_bfloat16 g_memh[S_ * B_ * D_], g_meml[S_ * B_ * D_];
#define WOFF_IN  0
#define WOFF_OUT (1536 * 512)
#define WOFF_L1  (WOFF_OUT + 512 * 512)
#define WOFF_L2  (WOFF_L1 + 2048 * 512)
#define WTOT     (WOFF_L2 + 512 * 2048)
__device__ __nv_bfloat16 g_wh[WTOT], g_wl[WTOT];

// ---------------- helpers ----------------
__device__ __forceinline__ uint32_t smem_u32(const void* p) {
    uint32_t a;
    asm("{ .reg .u64 t; cvta.to.shared.u64 t, %1; cvt.u32.u64 %0, t; }" : "=r"(a) : "l"(p));
    return a;
}
__device__ __forceinline__ void split1(float a, __nv_bfloat16& h, __nv_bfloat16& l) {
    h = __float2bfloat16(a);
    l = __float2bfloat16(a - __bfloat162float(h));
}
__device__ __forceinline__ void ldsm4(uint32_t* r, uint32_t addr) {
    asm volatile("ldmatrix.sync.aligned.m8n8.x4.shared.b16 {%0,%1,%2,%3}, [%4];"
        : "=r"(r[0]), "=r"(r[1]), "=r"(r[2]), "=r"(r[3]) : "r"(addr));
}
__device__ __forceinline__ void mma_bf16(float* d, const uint32_t* a, uint32_t b0, uint32_t b1) {
    asm volatile("mma.sync.aligned.m16n8k16.row.col.f32.bf16.bf16.f32 "
        "{%0,%1,%2,%3}, {%4,%5,%6,%7}, {%8,%9}, {%0,%1,%2,%3};"
        : "+f"(d[0]), "+f"(d[1]), "+f"(d[2]), "+f"(d[3])
        : "r"(a[0]), "r"(a[1]), "r"(a[2]), "r"(a[3]), "r"(b0), "r"(b1));
}
__device__ __forceinline__ void cpa16(uint32_t d, const void* s) {
    asm volatile("cp.async.cg.shared.global [%0], [%1], 16;" :: "r"(d), "l"(s));
}
#define CP_COMMIT() asm volatile("cp.async.commit_group;")
#define CP_WAIT1()  asm volatile("cp.async.wait_group 1;")

// ---------------- fp32 -> bf16 hi/lo split (vectorized) ----------------
__global__ void split_kernel(const float4* __restrict__ src,
                             __nv_bfloat162* __restrict__ hi,
                             __nv_bfloat162* __restrict__ lo, int n4) {
    int i = blockIdx.x * 256 + threadIdx.x;
    if (i >= n4) return;
    float4 v = src[i];
    __nv_bfloat16 hx, lx, hy, ly, hz, lz, hw, lw;
    split1(v.x, hx, lx); split1(v.y, hy, ly);
    split1(v.z, hz, lz); split1(v.w, hw, lw);
    hi[2 * i]     = __nv_bfloat162(hx, hy);
    hi[2 * i + 1] = __nv_bfloat162(hz, hw);
    lo[2 * i]     = __nv_bfloat162(lx, ly);
    lo[2 * i + 1] = __nv_bfloat162(lz, lw);
}

// ================= HMMA GEMM (cp.async double-buffered) =================
// CTA 128x128, K-chunk 32, 8 warps (2x4), warp tile 64x32, split-bf16 (3 MMA).
// smem rows padded to 40 bf16; 2 stages; MMAs ordered for reuse distance 4.
#define STG_ELEM (128 * 40)
#define STG_BYTE (STG_ELEM * 2)
#define GT_SMEM  (8 * STG_BYTE)   // 4 arrays x 2 stages = 81920 B

template<int RELU, int OSPLIT>
__global__ __launch_bounds__(256, 2) void gemm_bf16(
    const __nv_bfloat16* __restrict__ Ah, const __nv_bfloat16* __restrict__ Al,
    const __nv_bfloat16* __restrict__ Bh, const __nv_bfloat16* __restrict__ Bl,
    const float* __restrict__ bias, float* __restrict__ C,
    __nv_bfloat16* __restrict__ Ch, __nv_bfloat16* __restrict__ Cl,
    int M, int N, int K)
{
    extern __shared__ __nv_bfloat16 dsm[];
    __nv_bfloat16* sAh = dsm;
    __nv_bfloat16* sAl = dsm + 2 * STG_ELEM;
    __nv_bfloat16* sBh = dsm + 4 * STG_ELEM;
    __nv_bfloat16* sBl = dsm + 6 * STG_ELEM;

    int tid = threadIdx.x, lane = tid & 31, wid = tid >> 5;
    int m0 = blockIdx.y * 128, n0 = blockIdx.x * 128;
    int warp_m = wid >> 2, warp_n = wid & 3;

    float acc[4][4][4];
    #pragma unroll
    for (int i = 0; i < 4; i++)
        #pragma unroll
        for (int j = 0; j < 4; j++)
            #pragma unroll
            for (int k = 0; k < 4; k++) acc[i][j][k] = 0.f;

    uint32_t uAh = smem_u32(sAh), uAl = smem_u32(sAl);
    uint32_t uBh = smem_u32(sBh), uBl = smem_u32(sBl);

    uint32_t a_off = ((warp_m * 64 + (lane & 15)) * 40 + (lane >> 4) * 8) * 2;
    uint32_t b_off = ((warp_n * 32 + ((lane >> 4) & 1) * 8 + (lane & 7)) * 40
                      + ((lane >> 3) & 1) * 8) * 2;

    int lrow = tid >> 1;
    int lp   = (tid & 1) * 16;
    uint32_t sdst = (lrow * 40 + lp) * 2;   // bytes
    const __nv_bfloat16* Arow  = Ah + (size_t)(m0 + lrow) * K + lp;
    const __nv_bfloat16* Alrow = Al + (size_t)(m0 + lrow) * K + lp;
    const __nv_bfloat16* Brow  = Bh + (size_t)(n0 + lrow) * K + lp;
    const __nv_bfloat16* Blrow = Bl + (size_t)(n0 + lrow) * K + lp;

    auto prefetch = [&](int kc, int st) {
        uint32_t so = st * STG_BYTE + sdst;
        cpa16(uAh + so,      Arow + kc);
        cpa16(uAh + so + 16, Arow + kc + 8);
        cpa16(uAl + so,      Alrow + kc);
        cpa16(uAl + so + 16, Alrow + kc + 8);
        cpa16(uBh + so,      Brow + kc);
        cpa16(uBh + so + 16, Brow + kc + 8);
        cpa16(uBl + so,      Blrow + kc);
        cpa16(uBl + so + 16, Blrow + kc + 8);
        CP_COMMIT();
    };

    int nch = K >> 5;
    prefetch(0, 0);
    prefetch(32, 1);

    for (int c = 0; c < nch; c++) {
        CP_WAIT1();
        __syncthreads();
        uint32_t stb = (c & 1) * STG_BYTE;
        #pragma unroll
        for (int ks = 0; ks < 2; ks++) {
            uint32_t bh0[4], bh1[4], bl0[4], bl1[4];
            ldsm4(bh0, uBh + stb + b_off + ks * 32);
            ldsm4(bh1, uBh + stb + b_off + 1280 + ks * 32);
            ldsm4(bl0, uBl + stb + b_off + ks * 32);
            ldsm4(bl1, uBl + stb + b_off + 1280 + ks * 32);
            #pragma unroll
            for (int mi = 0; mi < 4; mi++) {
                uint32_t ah[4], al[4];
                ldsm4(ah, uAh + stb + a_off + mi * 1280 + ks * 32);
                ldsm4(al, uAl + stb + a_off + mi * 1280 + ks * 32);
                // reuse distance 4: cycle nj inside each split term
                mma_bf16(acc[mi][0], ah, bh0[0], bh0[1]);
                mma_bf16(acc[mi][1], ah, bh0[2], bh0[3]);
                mma_bf16(acc[mi][2], ah, bh1[0], bh1[1]);
                mma_bf16(acc[mi][3], ah, bh1[2], bh1[3]);
                mma_bf16(acc[mi][0], ah, bl0[0], bl0[1]);
                mma_bf16(acc[mi][1], ah, bl0[2], bl0[3]);
                mma_bf16(acc[mi][2], ah, bl1[0], bl1[1]);
                mma_bf16(acc[mi][3], ah, bl1[2], bl1[3]);
                mma_bf16(acc[mi][0], al, bh0[0], bh0[1]);
                mma_bf16(acc[mi][1], al, bh0[2], bh0[3]);
                mma_bf16(acc[mi][2], al, bh1[0], bh1[1]);
                mma_bf16(acc[mi][3], al, bh1[2], bh1[3]);
            }
        }
        __syncthreads();
        int nk = c + 2;
        if (nk < nch) prefetch(nk << 5, nk & 1);
    }

    // epilogue
    int r0 = lane >> 2, c0 = (lane & 3) * 2;
    int mbase = m0 + warp_m * 64, nbase = n0 + warp_n * 32;
    #pragma unroll
    for (int mi = 0; mi < 4; mi++) {
        #pragma unroll
        for (int nj = 0; nj < 4; nj++) {
            int nn = nbase + nj * 8 + c0;
            float b0 = bias[nn], b1 = bias[nn + 1];
            #pragma unroll
            for (int half = 0; half < 2; half++) {
                int mm = mbase + mi * 16 + r0 + half * 8;
                float v0 = acc[mi][nj][half * 2]     + b0;
                float v1 = acc[mi][nj][half * 2 + 1] + b1;
                if (RELU) { v0 = fmaxf(v0, 0.f); v1 = fmaxf(v1, 0.f); }
                size_t off = (size_t)mm * N + nn;
                if (OSPLIT) {
                    __nv_bfloat16 h0, l0, h1, l1;
                    split1(v0, h0, l0); split1(v1, h1, l1);
                    *(__nv_bfloat162*)(Ch + off) = __nv_bfloat162(h0, h1);
                    *(__nv_bfloat162*)(Cl + off) = __nv_bfloat162(l0, l1);
                } else {
                    *(float2*)(C + off) = make_float2(v0, v1);
                }
            }
        }
    }
}

// ---------------- query normalization (QaN) ----------------
__global__ void prep_q_kernel(const float* __restrict__ q) {
    int n = blockIdx.x / H_, h = blockIdx.x % H_;
    int lane = threadIdx.x;
    const float* base = q + n * D_ + h * DH;
    float v0 = base[lane];
    float v1 = base[lane + 32];
    float ss = v0 * v0 + v1 * v1;
    #pragma unroll
    for (int o = 16; o; o >>= 1) ss += __shfl_xor_sync(0xffffffffu, ss, o);
    float f = 1.0f / ((sqrtf(ss) + 1e-6f) * 8.0f * sqrtf(512.0f));
    g_qn[n * D_ + h * DH + lane]      = v0 * f;
    g_qn[n * D_ + h * DH + lane + 32] = v1 * f;
}

// ---------------- QaN local-attention block ----------------
__global__ __launch_bounds__(256) void qa_kernel(const float* __restrict__ tgt,
                                                 const float* __restrict__ wk) {
    extern __shared__ float sm[];
    float* kv  = sm;
    float* qs  = kv + 48 * 512;
    float* sim = qs + 10 * 512;
    float* wj  = sim + 10 * 48;

    int bx = blockIdx.x;
    int b = bx >> 7, m = bx & 127;
    int tid = threadIdx.x;

    for (int idx = tid; idx < 48 * 512; idx += 256) {
        int j = idx >> 9, d = idx & 511;
        int p = (m - 1) * W_ + j;
        kv[idx] = (p >= 0 && p < T_) ? tgt[(p * B_ + b) * D_ + d] : 0.0f;
    }
    for (int idx = tid; idx < 10 * 512; idx += 256) qs[idx] = g_qn[idx];
    __syncthreads();

    int w = tid >> 5, lane = tid & 31;
    for (int pw = w; pw < 480; pw += 8) {
        int n = pw / 48, j = pw % 48;
        const float* kr = kv + j * 512;
        const float* qr = qs + n * 512;
        float s = 0.f;
        for (int d = lane; d < 512; d += 32) s += kr[d] * qr[d];
        #pragma unroll
        for (int o = 16; o; o >>= 1) s += __shfl_xor_sync(0xffffffffu, s, o);
        if (lane == 0) {
            int win = m - 1 + (j >> 4);
            sim[n * 48 + j] = (win >= 0 && win < NW) ? s : NEGV;
        }
    }
    __syncthreads();

    for (int n = w; n < NQ_; n += 8) {
        float v0 = sim[n * 48 + lane];
        float v1 = (lane < 16) ? sim[n * 48 + 32 + lane] : NEGV;
        float mx = fmaxf(v0, v1);
        #pragma unroll
        for (int o = 16; o; o >>= 1) mx = fmaxf(mx, __shfl_xor_sync(0xffffffffu, mx, o));
        float e0 = __expf(v0 - mx);
        float e1 = (lane < 16) ? __expf(v1 - mx) : 0.f;
        float su = e0 + e1;
        #pragma unroll
        for (int o = 16; o; o >>= 1) su += __shfl_xor_sync(0xffffffffu, su, o);
        float inv = 1.0f / su;
        sim[n * 48 + lane] = e0 * inv;
        if (lane < 16) sim[n * 48 + 32 + lane] = e1 * inv;
    }
    __syncthreads();

    if (tid < 48) {
        float acc = 0.f;
        #pragma unroll
        for (int n = 0; n < NQ_; n++) acc += wk[n] * sim[n * 48 + tid];
        wj[tid] = acc;
    }
    __syncthreads();

    for (int d = tid; d < 512; d += 256) {
        float acc = 0.f;
        #pragma unroll
        for (int j = 0; j < 48; j++) acc += wj[j] * kv[j * 512 + d];
        g_qa[(b * NW + m) * D_ + d] = acc;
    }
}

// ---------------- residual add + LayerNorm ----------------
__device__ __forceinline__ float block_sum(float v, float* red) {
    int lane = threadIdx.x & 31, w = threadIdx.x >> 5;
    __syncthreads();
    #pragma unroll
    for (int o = 16; o; o >>= 1) v += __shfl_xor_sync(0xffffffffu, v, o);
    if (lane == 0) red[w] = v;
    __syncthreads();
    v = (lane < 8) ? red[lane] : 0.f;
    #pragma unroll
    for (int o = 4; o; o >>= 1) v += __shfl_xor_sync(0xffffffffu, v, o);
    return __shfl_sync(0xffffffffu, v, 0);
}

__global__ __launch_bounds__(256) void add_ln_kernel(const float* __restrict__ a,
                                                     const float* __restrict__ bsrc,
                                                     const float* __restrict__ g,
                                                     const float* __restrict__ be,
                                                     float* __restrict__ out,
                                                     __nv_bfloat16* __restrict__ oh,
                                                     __nv_bfloat16* __restrict__ ol,
                                                     int mode) {
    __shared__ float red[8];
    int r = blockIdx.x, tid = threadIdx.x;
    const float* ar = a + (size_t)r * D_;
    const float* br;
    if (mode == 1) {
        int t = r / B_, b = r % B_;
        br = bsrc + (size_t)(b * NW + (t >> 4)) * D_;
    } else {
        br = bsrc + (size_t)r * D_;
    }
    float x0 = ar[tid]       + br[tid];
    float x1 = ar[tid + 256] + br[tid + 256];
    float mu = block_sum(x0 + x1, red) * (1.0f / 512.0f);
    float d0 = x0 - mu, d1 = x1 - mu;
    float var = block_sum(d0 * d0 + d1 * d1, red) * (1.0f / 512.0f);
    float inv = rsqrtf(var + EPS);
    float y0 = d0 * inv * g[tid]       + be[tid];
    float y1 = d1 * inv * g[tid + 256] + be[tid + 256];
    size_t o0 = (size_t)r * D_ + tid, o1 = o0 + 256;
    out[o0] = y0;
    out[o1] = y1;
    if (oh) {
        __nv_bfloat16 h, l;
        split1(y0, h, l); oh[o0] = h; ol[o0] = l;
        split1(y1, h, l); oh[o1] = h; ol[o1] = l;
    }
}

// ---------------- cross attention (B,H) heads, S=512, dh=64 ----------------
#define SROW 513
#define ATTN_SMEM ((4096 + 8192 + 64 * SROW) * 4)

__global__ __launch_bounds__(256) void attn_kernel(const float* __restrict__ Q,
                                                   const float* __restrict__ KV,
                                                   __nv_bfloat16* __restrict__ Oh,
                                                   __nv_bfloat16* __restrict__ Ol) {
    extern __shared__ float sm[];
    float* Qt = sm;
    float* Kt = sm + 4096;
    float* Ss = Kt + 8192;

    int qt0 = blockIdx.x * 64, h = blockIdx.y, b = blockIdx.z;
    int tid = threadIdx.x;
    int ti = tid & 15, ts = tid >> 4;

    for (int idx = tid; idx < 4096; idx += 256) {
        int i = idx >> 6, d = idx & 63;
        Qt[d * 64 + i] = Q[((size_t)(qt0 + i) * B_ + b) * D_ + h * DH + d] * 0.125f;
    }

    for (int sch = 0; sch < 512; sch += 128) {
        __syncthreads();
        for (int idx = tid; idx < 8192; idx += 256) {
            int s = idx >> 6, d = idx & 63;
            Kt[d * 128 + s] = KV[((size_t)(sch + s) * B_ + b) * (2 * D_) + h * DH + d];
        }
        __syncthreads();
        float acc[4][8];
        #pragma unroll
        for (int a = 0; a < 4; a++)
            #pragma unroll
            for (int j = 0; j < 8; j++) acc[a][j] = 0.f;
        #pragma unroll 4
        for (int d = 0; d < 64; d++) {
            float4 q4 = *(const float4*)(Qt + d * 64 + ti * 4);
            float4 ka = *(const float4*)(Kt + d * 128 + ts * 8);
            float4 kb = *(const float4*)(Kt + d * 128 + ts * 8 + 4);
            float rq[4] = {q4.x, q4.y, q4.z, q4.w};
            float rk[8] = {ka.x, ka.y, ka.z, ka.w, kb.x, kb.y, kb.z, kb.w};
            #pragma unroll
            for (int a = 0; a < 4; a++)
                #pragma unroll
                for (int j = 0; j < 8; j++) acc[a][j] += rq[a] * rk[j];
        }
        #pragma unroll
        for (int a = 0; a < 4; a++)
            #pragma unroll
            for (int j = 0; j < 8; j++)
                Ss[(ti * 4 + a) * SROW + sch + ts * 8 + j] = acc[a][j];
    }
    __syncthreads();

    int w = tid >> 5, lane = tid & 31;
    for (int i = w * 8; i < w * 8 + 8; i++) {
        float* row = Ss + i * SROW;
        float mx = -INFINITY;
        for (int s = lane; s < 512; s += 32) mx = fmaxf(mx, row[s]);
        #pragma unroll
        for (int o = 16; o; o >>= 1) mx = fmaxf(mx, __shfl_xor_sync(0xffffffffu, mx, o));
        float su = 0.f;
        for (int s = lane; s < 512; s += 32) {
            float e = __expf(row[s] - mx);
            row[s] = e; su += e;
        }
        #pragma unroll
        for (int o = 16; o; o >>= 1) su += __shfl_xor_sync(0xffffffffu, su, o);
        float inv = 1.0f / su;
        for (int s = lane; s < 512; s += 32) row[s] *= inv;
    }

    float* Vs = Kt;
    int td = ts;
    float oacc[4][4];
    #pragma unroll
    for (int a = 0; a < 4; a++)
        #pragma unroll
        for (int j = 0; j < 4; j++) oacc[a][j] = 0.f;

    for (int sch = 0; sch < 512; sch += 64) {
        __syncthreads();
        for (int idx = tid; idx < 4096; idx += 256) {
            int s = idx >> 6, d = idx & 63;
            Vs[s * 68 + d] = KV[((size_t)(sch + s) * B_ + b) * (2 * D_) + D_ + h * DH + d];
        }
        __syncthreads();
        #pragma unroll 4
        for (int s = 0; s < 64; s++) {
            float4 v4 = *(const float4*)(Vs + s * 68 + td * 4);
            #pragma unroll
            for (int a = 0; a < 4; a++) {
                float p = Ss[(ti + 16 * a) * SROW + sch + s];
                oacc[a][0] += p * v4.x; oacc[a][1] += p * v4.y;
                oacc[a][2] += p * v4.z; oacc[a][3] += p * v4.w;
            }
        }
    }
    #pragma unroll
    for (int a = 0; a < 4; a++) {
        int i = ti + 16 * a;
        size_t base = ((size_t)(qt0 + i) * B_ + b) * D_ + h * DH + td * 4;
        __nv_bfloat16 h0, l0, h1, l1;
        split1(oacc[a][0], h0, l0); split1(oacc[a][1], h1, l1);
        *(__nv_bfloat162*)(Oh + base)     = __nv_bfloat162(h0, h1);
        *(__nv_bfloat162*)(Ol + base)     = __nv_bfloat162(l0, l1);
        split1(oacc[a][2], h0, l0); split1(oacc[a][3], h1, l1);
        *(__nv_bfloat162*)(Oh + base + 2) = __nv_bfloat162(h0, h1);
        *(__nv_bfloat162*)(Ol + base + 2) = __nv_bfloat162(l0, l1);
    }
}

#define QA_SMEM ((48 * 512 + 10 * 512 + 10 * 48 + 48) * 4)

// ---------------- host launcher ----------------
extern "C" void kernel_launch(void* const* d_in, const int* in_sizes, int n_in,
                              void* d_out, int out_size) {
    const float* tgt     = (const float*)d_in[0];
    const float* memory  = (const float*)d_in[1];
    const float* queries = (const float*)d_in[2];
    const float* wk      = (const float*)d_in[3];
    const float* in_w    = (const float*)d_in[4];
    const float* in_b    = (const float*)d_in[5];
    const float* out_w   = (const float*)d_in[6];
    const float* out_b   = (const float*)d_in[7];
    const float* l1w     = (const float*)d_in[8];
    const float* l1b     = (const float*)d_in[9];
    const float* l2w     = (const float*)d_in[10];
    const float* l2b     = (const float*)d_in[11];
    const float* ln1g    = (const float*)d_in[12];
    const float* ln1b    = (const float*)d_in[13];
    const float* ln2g    = (const float*)d_in[14];
    const float* ln2b    = (const float*)d_in[15];
    const float* ln3g    = (const float*)d_in[16];
    const float* ln3b    = (const float*)d_in[17];
    float* out = (float*)d_out;

    float *qa, *x1, *qb, *kv, *tmp, *x2;
    __nv_bfloat16 *x1h, *x1l, *x2h, *x2l, *obh, *obl, *hh, *hl, *memh, *meml, *wh, *wl;
    cudaGetSymbolAddress((void**)&qa,  g_qa);
    cudaGetSymbolAddress((void**)&x1,  g_x1);
    cudaGetSymbolAddress((void**)&qb,  g_q);
    cudaGetSymbolAddress((void**)&kv,  g_kv);
    cudaGetSymbolAddress((void**)&tmp, g_tmp);
    cudaGetSymbolAddress((void**)&x2,  g_x2);
    cudaGetSymbolAddress((void**)&x1h, g_x1h); cudaGetSymbolAddress((void**)&x1l, g_x1l);
    cudaGetSymbolAddress((void**)&x2h, g_x2h); cudaGetSymbolAddress((void**)&x2l, g_x2l);
    cudaGetSymbolAddress((void**)&obh, g_obh); cudaGetSymbolAddress((void**)&obl, g_obl);
    cudaGetSymbolAddress((void**)&hh,  g_hh);  cudaGetSymbolAddress((void**)&hl,  g_hl);
    cudaGetSymbolAddress((void**)&memh, g_memh); cudaGetSymbolAddress((void**)&meml, g_meml);
    cudaGetSymbolAddress((void**)&wh,  g_wh);  cudaGetSymbolAddress((void**)&wl,  g_wl);

    cudaFuncSetAttribute(qa_kernel,   cudaFuncAttributeMaxDynamicSharedMemorySize, QA_SMEM);
    cudaFuncSetAttribute(attn_kernel, cudaFuncAttributeMaxDynamicSharedMemorySize, ATTN_SMEM);
    cudaFuncSetAttribute(gemm_bf16<0,0>, cudaFuncAttributeMaxDynamicSharedMemorySize, GT_SMEM);
    cudaFuncSetAttribute(gemm_bf16<1,1>, cudaFuncAttributeMaxDynamicSharedMemorySize, GT_SMEM);

    const int MR = T_ * B_;   // 16384 rows

    // 0. split weights + memory into bf16 hi/lo
    auto splt = [&](const float* src, __nv_bfloat16* h, __nv_bfloat16* l, int n) {
        int n4 = n / 4;
        split_kernel<<<(n4 + 255) / 256, 256>>>((const float4*)src,
                                                (__nv_bfloat162*)h, (__nv_bfloat162*)l, n4);
    };
    splt(in_w,  wh + WOFF_IN,  wl + WOFF_IN,  1536 * 512);
    splt(out_w, wh + WOFF_OUT, wl + WOFF_OUT, 512 * 512);
    splt(l1w,   wh + WOFF_L1,  wl + WOFF_L1,  2048 * 512);
    splt(l2w,   wh + WOFF_L2,  wl + WOFF_L2,  512 * 2048);
    splt(memory, memh, meml, S_ * B_ * D_);

    // 1. QaN block + LN1
    prep_q_kernel<<<NQ_ * H_, 32>>>(queries);
    qa_kernel<<<B_ * NW, 256, QA_SMEM>>>(tgt, wk);
    add_ln_kernel<<<MR, 256>>>(tgt, qa, ln1g, ln1b, x1, x1h, x1l, 1);

    // 2. MHA projections (HMMA)
    gemm_bf16<0, 0><<<dim3(4, 128), 256, GT_SMEM>>>(x1h, x1l, wh + WOFF_IN, wl + WOFF_IN,
                                                    in_b, qb, nullptr, nullptr, MR, 512, 512);
    gemm_bf16<0, 0><<<dim3(8, 32), 256, GT_SMEM>>>(memh, meml, wh + WOFF_IN + 512 * 512,
                                                   wl + WOFF_IN + 512 * 512, in_b + 512,
                                                   kv, nullptr, nullptr, S_ * B_, 1024, 512);
    // 3. attention (fp32, emits split bf16 output)
    attn_kernel<<<dim3(T_ / 64, H_, B_), 256, ATTN_SMEM>>>(qb, kv, obh, obl);
    // 4. out proj + LN2
    gemm_bf16<0, 0><<<dim3(4, 128), 256, GT_SMEM>>>(obh, obl, wh + WOFF_OUT, wl + WOFF_OUT,
                                                    out_b, tmp, nullptr, nullptr, MR, 512, 512);
    add_ln_kernel<<<MR, 256>>>(x1, tmp, ln2g, ln2b, x2, x2h, x2l, 0);

    // 5. FFN + LN3
    gemm_bf16<1, 1><<<dim3(16, 128), 256, GT_SMEM>>>(x2h, x2l, wh + WOFF_L1, wl + WOFF_L1,
                                                     l1b, nullptr, hh, hl, MR, DFF_, 512);
    gemm_bf16<0, 0><<<dim3(4, 128), 256, GT_SMEM>>>(hh, hl, wh + WOFF_L2, wl + WOFF_L2,
                                                    l2b, tmp, nullptr, nullptr, MR, 512, DFF_);
    add_ln_kernel<<<MR, 256>>>(x2, tmp, ln3g, ln3b, out, nullptr, nullptr, 0);
}

// round 6
// speedup vs baseline: 1.2590x; 1.2590x over previous
#include <cuda_runtime.h>
#include <cuda_bf16.h>
#include <math.h>
#include <stdint.h>

#define T_   2048
#define B_   8
#define S_   512
#define D_   512
#define H_   8
#define DH   64
#define DFF_ 2048
#define NQ_  10
#define W_   16
#define NW   128
#define EPS  1e-5f
#define NEGV -1e30f

// ---------------- scratch (no dynamic allocation allowed) ----------------
__device__ float g_qn[NQ_ * D_];
__device__ float g_qa[B_ * NW * D_];
__device__ float g_x1[T_ * B_ * D_];
__device__ float g_q [T_ * B_ * D_];        // reused as bf16 qh|ql
__device__ float g_kv[S_ * B_ * 2 * D_];    // reused as bf16 kvh|kvl
__device__ float g_tmp[T_ * B_ * D_];
__device__ float g_x2[T_ * B_ * D_];

__device__ __nv_bfloat16 g_x1h[T_ * B_ * D_], g_x1l[T_ * B_ * D_];
__device__ __nv_bfloat16 g_x2h[T_ * B_ * D_], g_x2l[T_ * B_ * D_];
__device__ __nv_bfloat16 g_obh[T_ * B_ * D_], g_obl[T_ * B_ * D_];
__device__ __nv_bfloat16 g_hh [T_ * B_ * DFF_], g_hl [T_ * B_ * DFF_];
__device__ __nv_bfloat16 g_memh[S_ * B_ * D_], g_meml[S_ * B_ * D_];
#define WOFF_IN  0
#define WOFF_OUT (1536 * 512)
#define WOFF_L1  (WOFF_OUT + 512 * 512)
#define WOFF_L2  (WOFF_L1 + 2048 * 512)
#define WTOT     (WOFF_L2 + 512 * 2048)
__device__ __nv_bfloat16 g_wh[WTOT], g_wl[WTOT];

// ---------------- helpers ----------------
__device__ __forceinline__ uint32_t smem_u32(const void* p) {
    uint32_t a;
    asm("{ .reg .u64 t; cvta.to.shared.u64 t, %1; cvt.u32.u64 %0, t; }" : "=r"(a) : "l"(p));
    return a;
}
__device__ __forceinline__ void split1(float a, __nv_bfloat16& h, __nv_bfloat16& l) {
    h = __float2bfloat16(a);
    l = __float2bfloat16(a - __bfloat162float(h));
}
__device__ __forceinline__ void ldsm4(uint32_t* r, uint32_t addr) {
    asm volatile("ldmatrix.sync.aligned.m8n8.x4.shared.b16 {%0,%1,%2,%3}, [%4];"
        : "=r"(r[0]), "=r"(r[1]), "=r"(r[2]), "=r"(r[3]) : "r"(addr));
}
__device__ __forceinline__ void ldsm4t(uint32_t* r, uint32_t addr) {
    asm volatile("ldmatrix.sync.aligned.m8n8.x4.trans.shared.b16 {%0,%1,%2,%3}, [%4];"
        : "=r"(r[0]), "=r"(r[1]), "=r"(r[2]), "=r"(r[3]) : "r"(addr));
}
__device__ __forceinline__ void mma_bf16(float* d, const uint32_t* a, uint32_t b0, uint32_t b1) {
    asm volatile("mma.sync.aligned.m16n8k16.row.col.f32.bf16.bf16.f32 "
        "{%0,%1,%2,%3}, {%4,%5,%6,%7}, {%8,%9}, {%0,%1,%2,%3};"
        : "+f"(d[0]), "+f"(d[1]), "+f"(d[2]), "+f"(d[3])
        : "r"(a[0]), "r"(a[1]), "r"(a[2]), "r"(a[3]), "r"(b0), "r"(b1));
}
__device__ __forceinline__ void cpa16(uint32_t d, const void* s) {
    asm volatile("cp.async.cg.shared.global [%0], [%1], 16;" :: "r"(d), "l"(s));
}
#define CP_COMMIT() asm volatile("cp.async.commit_group;")
#define CP_WAIT1()  asm volatile("cp.async.wait_group 1;")

// ---------------- fused fp32 -> bf16 hi/lo split (all weights + memory) ----------------
__device__ __forceinline__ void split4_store(float4 v, __nv_bfloat162* dh, __nv_bfloat162* dl, int j) {
    __nv_bfloat16 hx, lx, hy, ly, hz, lz, hw, lw;
    split1(v.x, hx, lx); split1(v.y, hy, ly);
    split1(v.z, hz, lz); split1(v.w, hw, lw);
    dh[2 * j]     = __nv_bfloat162(hx, hy);
    dh[2 * j + 1] = __nv_bfloat162(hz, hw);
    dl[2 * j]     = __nv_bfloat162(lx, ly);
    dl[2 * j + 1] = __nv_bfloat162(lz, lw);
}

__global__ void split_all_kernel(const float4* __restrict__ inw, const float4* __restrict__ outw,
                                 const float4* __restrict__ l1w, const float4* __restrict__ l2w,
                                 const float4* __restrict__ mem,
                                 __nv_bfloat16* __restrict__ wh, __nv_bfloat16* __restrict__ wl,
                                 __nv_bfloat16* __restrict__ memh, __nv_bfloat16* __restrict__ meml) {
    int i = blockIdx.x * 256 + threadIdx.x;
    const int n0 = 1536 * 512 / 4;
    const int n1 = n0 + 512 * 512 / 4;
    const int n2 = n1 + 2048 * 512 / 4;
    const int n3 = n2 + 512 * 2048 / 4;
    const int n4 = n3 + S_ * B_ * D_ / 4;
    if (i >= n4) return;
    const float4* src; __nv_bfloat162 *dh, *dl; int j;
    if (i < n0)      { j = i;      src = inw;  dh = (__nv_bfloat162*)(wh + WOFF_IN);  dl = (__nv_bfloat162*)(wl + WOFF_IN); }
    else if (i < n1) { j = i - n0; src = outw; dh = (__nv_bfloat162*)(wh + WOFF_OUT); dl = (__nv_bfloat162*)(wl + WOFF_OUT); }
    else if (i < n2) { j = i - n1; src = l1w;  dh = (__nv_bfloat162*)(wh + WOFF_L1);  dl = (__nv_bfloat162*)(wl + WOFF_L1); }
    else if (i < n3) { j = i - n2; src = l2w;  dh = (__nv_bfloat162*)(wh + WOFF_L2);  dl = (__nv_bfloat162*)(wl + WOFF_L2); }
    else             { j = i - n3; src = mem;  dh = (__nv_bfloat162*)memh;            dl = (__nv_bfloat162*)meml; }
    split4_store(src[j], dh, dl, j);
}

// ================= HMMA GEMM (cp.async double-buffered) =================
#define STG_ELEM (128 * 40)
#define STG_BYTE (STG_ELEM * 2)
#define GT_SMEM  (8 * STG_BYTE)

template<int RELU, int OSPLIT>
__global__ __launch_bounds__(256, 2) void gemm_bf16(
    const __nv_bfloat16* __restrict__ Ah, const __nv_bfloat16* __restrict__ Al,
    const __nv_bfloat16* __restrict__ Bh, const __nv_bfloat16* __restrict__ Bl,
    const float* __restrict__ bias, float* __restrict__ C,
    __nv_bfloat16* __restrict__ Ch, __nv_bfloat16* __restrict__ Cl,
    int M, int N, int K)
{
    extern __shared__ __nv_bfloat16 dsm[];
    __nv_bfloat16* sAh = dsm;
    __nv_bfloat16* sAl = dsm + 2 * STG_ELEM;
    __nv_bfloat16* sBh = dsm + 4 * STG_ELEM;
    __nv_bfloat16* sBl = dsm + 6 * STG_ELEM;

    int tid = threadIdx.x, lane = tid & 31, wid = tid >> 5;
    int m0 = blockIdx.y * 128, n0 = blockIdx.x * 128;
    int warp_m = wid >> 2, warp_n = wid & 3;

    float acc[4][4][4];
    #pragma unroll
    for (int i = 0; i < 4; i++)
        #pragma unroll
        for (int j = 0; j < 4; j++)
            #pragma unroll
            for (int k = 0; k < 4; k++) acc[i][j][k] = 0.f;

    uint32_t uAh = smem_u32(sAh), uAl = smem_u32(sAl);
    uint32_t uBh = smem_u32(sBh), uBl = smem_u32(sBl);

    uint32_t a_off = ((warp_m * 64 + (lane & 15)) * 40 + (lane >> 4) * 8) * 2;
    uint32_t b_off = ((warp_n * 32 + ((lane >> 4) & 1) * 8 + (lane & 7)) * 40
                      + ((lane >> 3) & 1) * 8) * 2;

    int lrow = tid >> 1;
    int lp   = (tid & 1) * 16;
    uint32_t sdst = (lrow * 40 + lp) * 2;
    const __nv_bfloat16* Arow  = Ah + (size_t)(m0 + lrow) * K + lp;
    const __nv_bfloat16* Alrow = Al + (size_t)(m0 + lrow) * K + lp;
    const __nv_bfloat16* Brow  = Bh + (size_t)(n0 + lrow) * K + lp;
    const __nv_bfloat16* Blrow = Bl + (size_t)(n0 + lrow) * K + lp;

    auto prefetch = [&](int kc, int st) {
        uint32_t so = st * STG_BYTE + sdst;
        cpa16(uAh + so,      Arow + kc);
        cpa16(uAh + so + 16, Arow + kc + 8);
        cpa16(uAl + so,      Alrow + kc);
        cpa16(uAl + so + 16, Alrow + kc + 8);
        cpa16(uBh + so,      Brow + kc);
        cpa16(uBh + so + 16, Brow + kc + 8);
        cpa16(uBl + so,      Blrow + kc);
        cpa16(uBl + so + 16, Blrow + kc + 8);
        CP_COMMIT();
    };

    int nch = K >> 5;
    prefetch(0, 0);
    prefetch(32, 1);

    for (int c = 0; c < nch; c++) {
        CP_WAIT1();
        __syncthreads();
        uint32_t stb = (c & 1) * STG_BYTE;
        #pragma unroll
        for (int ks = 0; ks < 2; ks++) {
            uint32_t bh0[4], bh1[4], bl0[4], bl1[4];
            ldsm4(bh0, uBh + stb + b_off + ks * 32);
            ldsm4(bh1, uBh + stb + b_off + 1280 + ks * 32);
            ldsm4(bl0, uBl + stb + b_off + ks * 32);
            ldsm4(bl1, uBl + stb + b_off + 1280 + ks * 32);
            #pragma unroll
            for (int mi = 0; mi < 4; mi++) {
                uint32_t ah[4], al[4];
                ldsm4(ah, uAh + stb + a_off + mi * 1280 + ks * 32);
                ldsm4(al, uAl + stb + a_off + mi * 1280 + ks * 32);
                mma_bf16(acc[mi][0], ah, bh0[0], bh0[1]);
                mma_bf16(acc[mi][1], ah, bh0[2], bh0[3]);
                mma_bf16(acc[mi][2], ah, bh1[0], bh1[1]);
                mma_bf16(acc[mi][3], ah, bh1[2], bh1[3]);
                mma_bf16(acc[mi][0], ah, bl0[0], bl0[1]);
                mma_bf16(acc[mi][1], ah, bl0[2], bl0[3]);
                mma_bf16(acc[mi][2], ah, bl1[0], bl1[1]);
                mma_bf16(acc[mi][3], ah, bl1[2], bl1[3]);
                mma_bf16(acc[mi][0], al, bh0[0], bh0[1]);
                mma_bf16(acc[mi][1], al, bh0[2], bh0[3]);
                mma_bf16(acc[mi][2], al, bh1[0], bh1[1]);
                mma_bf16(acc[mi][3], al, bh1[2], bh1[3]);
            }
        }
        __syncthreads();
        int nk = c + 2;
        if (nk < nch) prefetch(nk << 5, nk & 1);
    }

    int r0 = lane >> 2, c0 = (lane & 3) * 2;
    int mbase = m0 + warp_m * 64, nbase = n0 + warp_n * 32;
    #pragma unroll
    for (int mi = 0; mi < 4; mi++) {
        #pragma unroll
        for (int nj = 0; nj < 4; nj++) {
            int nn = nbase + nj * 8 + c0;
            float b0 = bias[nn], b1 = bias[nn + 1];
            #pragma unroll
            for (int half = 0; half < 2; half++) {
                int mm = mbase + mi * 16 + r0 + half * 8;
                float v0 = acc[mi][nj][half * 2]     + b0;
                float v1 = acc[mi][nj][half * 2 + 1] + b1;
                if (RELU) { v0 = fmaxf(v0, 0.f); v1 = fmaxf(v1, 0.f); }
                size_t off = (size_t)mm * N + nn;
                if (OSPLIT) {
                    __nv_bfloat16 h0, l0, h1, l1;
                    split1(v0, h0, l0); split1(v1, h1, l1);
                    *(__nv_bfloat162*)(Ch + off) = __nv_bfloat162(h0, h1);
                    *(__nv_bfloat162*)(Cl + off) = __nv_bfloat162(l0, l1);
                } else {
                    *(float2*)(C + off) = make_float2(v0, v1);
                }
            }
        }
    }
}

// ---------------- query normalization (QaN) ----------------
__global__ void prep_q_kernel(const float* __restrict__ q) {
    int n = blockIdx.x / H_, h = blockIdx.x % H_;
    int lane = threadIdx.x;
    const float* base = q + n * D_ + h * DH;
    float v0 = base[lane];
    float v1 = base[lane + 32];
    float ss = v0 * v0 + v1 * v1;
    #pragma unroll
    for (int o = 16; o; o >>= 1) ss += __shfl_xor_sync(0xffffffffu, ss, o);
    float f = 1.0f / ((sqrtf(ss) + 1e-6f) * 8.0f * sqrtf(512.0f));
    g_qn[n * D_ + h * DH + lane]      = v0 * f;
    g_qn[n * D_ + h * DH + lane + 32] = v1 * f;
}

// ---------------- QaN local-attention block ----------------
__global__ __launch_bounds__(256) void qa_kernel(const float* __restrict__ tgt,
                                                 const float* __restrict__ wk) {
    extern __shared__ float sm[];
    float* kv  = sm;
    float* qs  = kv + 48 * 512;
    float* sim = qs + 10 * 512;
    float* wj  = sim + 10 * 48;

    int bx = blockIdx.x;
    int b = bx >> 7, m = bx & 127;
    int tid = threadIdx.x;

    for (int idx = tid; idx < 48 * 512; idx += 256) {
        int j = idx >> 9, d = idx & 511;
        int p = (m - 1) * W_ + j;
        kv[idx] = (p >= 0 && p < T_) ? tgt[(p * B_ + b) * D_ + d] : 0.0f;
    }
    for (int idx = tid; idx < 10 * 512; idx += 256) qs[idx] = g_qn[idx];
    __syncthreads();

    int w = tid >> 5, lane = tid & 31;
    for (int pw = w; pw < 480; pw += 8) {
        int n = pw / 48, j = pw % 48;
        const float* kr = kv + j * 512;
        const float* qr = qs + n * 512;
        float s = 0.f;
        for (int d = lane; d < 512; d += 32) s += kr[d] * qr[d];
        #pragma unroll
        for (int o = 16; o; o >>= 1) s += __shfl_xor_sync(0xffffffffu, s, o);
        if (lane == 0) {
            int win = m - 1 + (j >> 4);
            sim[n * 48 + j] = (win >= 0 && win < NW) ? s : NEGV;
        }
    }
    __syncthreads();

    for (int n = w; n < NQ_; n += 8) {
        float v0 = sim[n * 48 + lane];
        float v1 = (lane < 16) ? sim[n * 48 + 32 + lane] : NEGV;
        float mx = fmaxf(v0, v1);
        #pragma unroll
        for (int o = 16; o; o >>= 1) mx = fmaxf(mx, __shfl_xor_sync(0xffffffffu, mx, o));
        float e0 = __expf(v0 - mx);
        float e1 = (lane < 16) ? __expf(v1 - mx) : 0.f;
        float su = e0 + e1;
        #pragma unroll
        for (int o = 16; o; o >>= 1) su += __shfl_xor_sync(0xffffffffu, su, o);
        float inv = 1.0f / su;
        sim[n * 48 + lane] = e0 * inv;
        if (lane < 16) sim[n * 48 + 32 + lane] = e1 * inv;
    }
    __syncthreads();

    if (tid < 48) {
        float acc = 0.f;
        #pragma unroll
        for (int n = 0; n < NQ_; n++) acc += wk[n] * sim[n * 48 + tid];
        wj[tid] = acc;
    }
    __syncthreads();

    for (int d = tid; d < 512; d += 256) {
        float acc = 0.f;
        #pragma unroll
        for (int j = 0; j < 48; j++) acc += wj[j] * kv[j * 512 + d];
        g_qa[(b * NW + m) * D_ + d] = acc;
    }
}

// ---------------- residual add + LayerNorm ----------------
__device__ __forceinline__ float block_sum(float v, float* red) {
    int lane = threadIdx.x & 31, w = threadIdx.x >> 5;
    __syncthreads();
    #pragma unroll
    for (int o = 16; o; o >>= 1) v += __shfl_xor_sync(0xffffffffu, v, o);
    if (lane == 0) red[w] = v;
    __syncthreads();
    v = (lane < 8) ? red[lane] : 0.f;
    #pragma unroll
    for (int o = 4; o; o >>= 1) v += __shfl_xor_sync(0xffffffffu, v, o);
    return __shfl_sync(0xffffffffu, v, 0);
}

__global__ __launch_bounds__(256) void add_ln_kernel(const float* __restrict__ a,
                                                     const float* __restrict__ bsrc,
                                                     const float* __restrict__ g,
                                                     const float* __restrict__ be,
                                                     float* __restrict__ out,
                                                     __nv_bfloat16* __restrict__ oh,
                                                     __nv_bfloat16* __restrict__ ol,
                                                     int mode) {
    __shared__ float red[8];
    int r = blockIdx.x, tid = threadIdx.x;
    const float* ar = a + (size_t)r * D_;
    const float* br;
    if (mode == 1) {
        int t = r / B_, b = r % B_;
        br = bsrc + (size_t)(b * NW + (t >> 4)) * D_;
    } else {
        br = bsrc + (size_t)r * D_;
    }
    float x0 = ar[tid]       + br[tid];
    float x1 = ar[tid + 256] + br[tid + 256];
    float mu = block_sum(x0 + x1, red) * (1.0f / 512.0f);
    float d0 = x0 - mu, d1 = x1 - mu;
    float var = block_sum(d0 * d0 + d1 * d1, red) * (1.0f / 512.0f);
    float inv = rsqrtf(var + EPS);
    float y0 = d0 * inv * g[tid]       + be[tid];
    float y1 = d1 * inv * g[tid + 256] + be[tid + 256];
    size_t o0 = (size_t)r * D_ + tid, o1 = o0 + 256;
    out[o0] = y0;
    out[o1] = y1;
    if (oh) {
        __nv_bfloat16 h, l;
        split1(y0, h, l); oh[o0] = h; ol[o0] = l;
        split1(y1, h, l); oh[o1] = h; ol[o1] = l;
    }
}

// ---------------- cross attention v2: full HMMA (split bf16) ----------------
// CTA: 64 queries x full S=512 for one (b,h). 256 threads.
// smem: Ss fp32 [64][524]; Q hi/lo [64][72] bf16; K/V chunk hi/lo [128][72] bf16.
#define SROW2  524
#define SROWB  (SROW2 * 4)
#define AT_QH  (64 * SROW2 * 4)
#define AT_QL  (AT_QH + 64 * 72 * 2)
#define AT_KH  (AT_QL + 64 * 72 * 2)
#define AT_KL  (AT_KH + 128 * 72 * 2)
#define ATTN2_SMEM (AT_KL + 128 * 72 * 2)   // 189440 bytes

__global__ __launch_bounds__(256, 1) void attn2_kernel(
    const __nv_bfloat16* __restrict__ Qh, const __nv_bfloat16* __restrict__ Ql,
    const __nv_bfloat16* __restrict__ KVh, const __nv_bfloat16* __restrict__ KVl,
    __nv_bfloat16* __restrict__ Oh, __nv_bfloat16* __restrict__ Ol)
{
    extern __shared__ char smc[];
    float* Ss = (float*)smc;
    uint32_t uS  = smem_u32(smc);
    uint32_t uQh = uS + AT_QH, uQl = uS + AT_QL;
    uint32_t uKh = uS + AT_KH, uKl = uS + AT_KL;

    int qt0 = blockIdx.x * 64, h = blockIdx.y, b = blockIdx.z;
    int tid = threadIdx.x, lane = tid & 31, wid = tid >> 5;
    int r0 = lane >> 2, c0 = (lane & 3) * 2;

    // --- load K/V chunk: 128 rows x 64 cols bf16, row stride 72 ---
    auto loadKV = [&](int sch, int col) {
        for (int idx = tid; idx < 1024; idx += 256) {
            int s = idx >> 3, dg = (idx & 7) * 8;
            size_t go = ((size_t)(sch + s) * B_ + b) * 1024 + col + h * DH + dg;
            *(uint4*)(smc + AT_KH + (s * 72 + dg) * 2) = *(const uint4*)(KVh + go);
            *(uint4*)(smc + AT_KL + (s * 72 + dg) * 2) = *(const uint4*)(KVl + go);
        }
    };

    // --- load Q tile [64 x 64], scaled by 1/8 (exact exponent shift) ---
    {
        __nv_bfloat162 sc = __floats2bfloat162_rn(0.125f, 0.125f);
        for (int idx = tid; idx < 64 * 32; idx += 256) {
            int i = idx >> 5, dp = idx & 31;
            size_t go = (((size_t)(qt0 + i) * B_ + b) * D_ + h * DH) / 2 + dp;
            __nv_bfloat162 vh = ((const __nv_bfloat162*)Qh)[go];
            __nv_bfloat162 vl = ((const __nv_bfloat162*)Ql)[go];
            ((__nv_bfloat162*)(smc + AT_QH))[i * 36 + dp] = __hmul2(vh, sc);
            ((__nv_bfloat162*)(smc + AT_QL))[i * 36 + dp] = __hmul2(vl, sc);
        }
    }
    loadKV(0, 0);
    __syncthreads();

    // ===== phase 1: scores = Q Kt (64 x 512), warps (wq 2) x (ws 4) =====
    int wq = wid >> 2, ws = wid & 3;
    uint32_t a_lo = ((lane & 15) * 72 + (lane >> 4) * 8) * 2;
    uint32_t b_lo = ((((lane >> 4) & 1) * 8 + (lane & 7)) * 72 + ((lane >> 3) & 1) * 8) * 2;

    uint32_t aqh[2][4][4], aql[2][4][4];
    #pragma unroll
    for (int mi = 0; mi < 2; mi++)
        #pragma unroll
        for (int ks = 0; ks < 4; ks++) {
            ldsm4(aqh[mi][ks], uQh + (wq * 32 + mi * 16) * 144 + a_lo + ks * 32);
            ldsm4(aql[mi][ks], uQl + (wq * 32 + mi * 16) * 144 + a_lo + ks * 32);
        }

    for (int c = 0; c < 4; c++) {
        int sch = c * 128;
        float acc[2][4][4];
        #pragma unroll
        for (int i = 0; i < 2; i++)
            #pragma unroll
            for (int j = 0; j < 4; j++)
                #pragma unroll
                for (int k = 0; k < 4; k++) acc[i][j][k] = 0.f;

        #pragma unroll
        for (int ks = 0; ks < 4; ks++) {
            uint32_t kh0[4], kh1[4], kl0[4], kl1[4];
            uint32_t kb = uKh + (ws * 32) * 144 + b_lo + ks * 32;
            ldsm4(kh0, kb);
            ldsm4(kh1, kb + 16 * 144);
            uint32_t klb = uKl + (ws * 32) * 144 + b_lo + ks * 32;
            ldsm4(kl0, klb);
            ldsm4(kl1, klb + 16 * 144);
            #pragma unroll
            for (int mi = 0; mi < 2; mi++) {
                mma_bf16(acc[mi][0], aqh[mi][ks], kh0[0], kh0[1]);
                mma_bf16(acc[mi][1], aqh[mi][ks], kh0[2], kh0[3]);
                mma_bf16(acc[mi][2], aqh[mi][ks], kh1[0], kh1[1]);
                mma_bf16(acc[mi][3], aqh[mi][ks], kh1[2], kh1[3]);
                mma_bf16(acc[mi][0], aqh[mi][ks], kl0[0], kl0[1]);
                mma_bf16(acc[mi][1], aqh[mi][ks], kl0[2], kl0[3]);
                mma_bf16(acc[mi][2], aqh[mi][ks], kl1[0], kl1[1]);
                mma_bf16(acc[mi][3], aqh[mi][ks], kl1[2], kl1[3]);
                mma_bf16(acc[mi][0], aql[mi][ks], kh0[0], kh0[1]);
                mma_bf16(acc[mi][1], aql[mi][ks], kh0[2], kh0[3]);
                mma_bf16(acc[mi][2], aql[mi][ks], kh1[0], kh1[1]);
                mma_bf16(acc[mi][3], aql[mi][ks], kh1[2], kh1[3]);
            }
        }
        #pragma unroll
        for (int mi = 0; mi < 2; mi++)
            #pragma unroll
            for (int nj = 0; nj < 4; nj++)
                #pragma unroll
                for (int half = 0; half < 2; half++) {
                    int qr = wq * 32 + mi * 16 + r0 + half * 8;
                    int scol = sch + ws * 32 + nj * 8 + c0;
                    *(float2*)&Ss[qr * SROW2 + scol] =
                        make_float2(acc[mi][nj][half * 2], acc[mi][nj][half * 2 + 1]);
                }
        __syncthreads();
        if (c < 3) { loadKV(sch + 128, 0); __syncthreads(); }
    }

    // ===== phase 2: softmax + in-place convert P -> bf16 hi|lo =====
    {
        int i0 = wid * 8;
        for (int i = i0; i < i0 + 8; i++) {
            float* row = Ss + i * SROW2;
            float v[16];
            #pragma unroll
            for (int j = 0; j < 16; j++) v[j] = row[lane + 32 * j];
            float mx = v[0];
            #pragma unroll
            for (int j = 1; j < 16; j++) mx = fmaxf(mx, v[j]);
            #pragma unroll
            for (int o = 16; o; o >>= 1) mx = fmaxf(mx, __shfl_xor_sync(0xffffffffu, mx, o));
            float su = 0.f;
            #pragma unroll
            for (int j = 0; j < 16; j++) { v[j] = __expf(v[j] - mx); su += v[j]; }
            #pragma unroll
            for (int o = 16; o; o >>= 1) su += __shfl_xor_sync(0xffffffffu, su, o);
            float inv = 1.0f / su;
            __syncwarp();
            __nv_bfloat16* rh = (__nv_bfloat16*)row;
            __nv_bfloat16* rl = rh + 512;
            #pragma unroll
            for (int j = 0; j < 16; j++) {
                __nv_bfloat16 hh, ll;
                split1(v[j] * inv, hh, ll);
                rh[lane + 32 * j] = hh;
                rl[lane + 32 * j] = ll;
            }
        }
    }
    __syncthreads();

    // ===== phase 3: O = P V (64 x 64), warps (wq2 4) x (wd 2) =====
    int wq2 = wid >> 1, wd = wid & 1;
    float oacc[4][4];
    #pragma unroll
    for (int j = 0; j < 4; j++)
        #pragma unroll
        for (int k = 0; k < 4; k++) oacc[j][k] = 0.f;

    uint32_t pa = uS + (wq2 * 16 + (lane & 15)) * SROWB + (lane >> 4) * 16;
    uint32_t vb_lo = ((lane & 15) * 72 + (wd * 32 + (lane >> 4) * 8)) * 2;

    for (int c = 0; c < 4; c++) {
        loadKV(c * 128, 512);
        __syncthreads();
        #pragma unroll
        for (int ks = 0; ks < 8; ks++) {
            uint32_t ph[4], pl[4];
            uint32_t paddr = pa + (c * 128 + ks * 16) * 2;
            ldsm4(ph, paddr);
            ldsm4(pl, paddr + 1024);
            uint32_t vh0[4], vh1[4], vl0[4], vl1[4];
            uint32_t va = uKh + vb_lo + ks * 16 * 144;
            ldsm4t(vh0, va);
            ldsm4t(vh1, va + 32);
            uint32_t vla = uKl + vb_lo + ks * 16 * 144;
            ldsm4t(vl0, vla);
            ldsm4t(vl1, vla + 32);
            mma_bf16(oacc[0], ph, vh0[0], vh0[1]);
            mma_bf16(oacc[1], ph, vh0[2], vh0[3]);
            mma_bf16(oacc[2], ph, vh1[0], vh1[1]);
            mma_bf16(oacc[3], ph, vh1[2], vh1[3]);
            mma_bf16(oacc[0], ph, vl0[0], vl0[1]);
            mma_bf16(oacc[1], ph, vl0[2], vl0[3]);
            mma_bf16(oacc[2], ph, vl1[0], vl1[1]);
            mma_bf16(oacc[3], ph, vl1[2], vl1[3]);
            mma_bf16(oacc[0], pl, vh0[0], vh0[1]);
            mma_bf16(oacc[1], pl, vh0[2], vh0[3]);
            mma_bf16(oacc[2], pl, vh1[0], vh1[1]);
            mma_bf16(oacc[3], pl, vh1[2], vh1[3]);
        }
        __syncthreads();
    }

    #pragma unroll
    for (int nj = 0; nj < 4; nj++)
        #pragma unroll
        for (int half = 0; half < 2; half++) {
            int q = qt0 + wq2 * 16 + r0 + half * 8;
            int d = wd * 32 + nj * 8 + c0;
            size_t off = ((size_t)q * B_ + b) * D_ + h * DH + d;
            __nv_bfloat16 h0, l0, h1, l1;
            split1(oacc[nj][half * 2], h0, l0);
            split1(oacc[nj][half * 2 + 1], h1, l1);
            *(__nv_bfloat162*)(Oh + off) = __nv_bfloat162(h0, h1);
            *(__nv_bfloat162*)(Ol + off) = __nv_bfloat162(l0, l1);
        }
}

#define QA_SMEM ((48 * 512 + 10 * 512 + 10 * 48 + 48) * 4)

// ---------------- host launcher ----------------
extern "C" void kernel_launch(void* const* d_in, const int* in_sizes, int n_in,
                              void* d_out, int out_size) {
    const float* tgt     = (const float*)d_in[0];
    const float* memory  = (const float*)d_in[1];
    const float* queries = (const float*)d_in[2];
    const float* wk      = (const float*)d_in[3];
    const float* in_w    = (const float*)d_in[4];
    const float* in_b    = (const float*)d_in[5];
    const float* out_w   = (const float*)d_in[6];
    const float* out_b   = (const float*)d_in[7];
    const float* l1w     = (const float*)d_in[8];
    const float* l1b     = (const float*)d_in[9];
    const float* l2w     = (const float*)d_in[10];
    const float* l2b     = (const float*)d_in[11];
    const float* ln1g    = (const float*)d_in[12];
    const float* ln1b    = (const float*)d_in[13];
    const float* ln2g    = (const float*)d_in[14];
    const float* ln2b    = (const float*)d_in[15];
    const float* ln3g    = (const float*)d_in[16];
    const float* ln3b    = (const float*)d_in[17];
    float* out = (float*)d_out;

    float *qa, *x1, *qb, *kv, *tmp, *x2;
    __nv_bfloat16 *x1h, *x1l, *x2h, *x2l, *obh, *obl, *hh, *hl, *memh, *meml, *wh, *wl;
    cudaGetSymbolAddress((void**)&qa,  g_qa);
    cudaGetSymbolAddress((void**)&x1,  g_x1);
    cudaGetSymbolAddress((void**)&qb,  g_q);
    cudaGetSymbolAddress((void**)&kv,  g_kv);
    cudaGetSymbolAddress((void**)&tmp, g_tmp);
    cudaGetSymbolAddress((void**)&x2,  g_x2);
    cudaGetSymbolAddress((void**)&x1h, g_x1h); cudaGetSymbolAddress((void**)&x1l, g_x1l);
    cudaGetSymbolAddress((void**)&x2h, g_x2h); cudaGetSymbolAddress((void**)&x2l, g_x2l);
    cudaGetSymbolAddress((void**)&obh, g_obh); cudaGetSymbolAddress((void**)&obl, g_obl);
    cudaGetSymbolAddress((void**)&hh,  g_hh);  cudaGetSymbolAddress((void**)&hl,  g_hl);
    cudaGetSymbolAddress((void**)&memh, g_memh); cudaGetSymbolAddress((void**)&meml, g_meml);
    cudaGetSymbolAddress((void**)&wh,  g_wh);  cudaGetSymbolAddress((void**)&wl,  g_wl);

    // reinterpret fp32 scratch as bf16 hi|lo pairs
    __nv_bfloat16* qh  = (__nv_bfloat16*)qb;
    __nv_bfloat16* ql  = qh + (size_t)T_ * B_ * D_;
    __nv_bfloat16* kvh = (__nv_bfloat16*)kv;
    __nv_bfloat16* kvl = kvh + (size_t)S_ * B_ * 2 * D_;

    cudaFuncSetAttribute(qa_kernel,    cudaFuncAttributeMaxDynamicSharedMemorySize, QA_SMEM);
    cudaFuncSetAttribute(attn2_kernel, cudaFuncAttributeMaxDynamicSharedMemorySize, ATTN2_SMEM);
    cudaFuncSetAttribute(gemm_bf16<0,0>, cudaFuncAttributeMaxDynamicSharedMemorySize, GT_SMEM);
    cudaFuncSetAttribute(gemm_bf16<0,1>, cudaFuncAttributeMaxDynamicSharedMemorySize, GT_SMEM);
    cudaFuncSetAttribute(gemm_bf16<1,1>, cudaFuncAttributeMaxDynamicSharedMemorySize, GT_SMEM);

    const int MR = T_ * B_;

    // 1. fused split of all weights + memory (one launch)
    split_all_kernel<<<5120, 256>>>((const float4*)in_w, (const float4*)out_w,
                                    (const float4*)l1w, (const float4*)l2w,
                                    (const float4*)memory, wh, wl, memh, meml);
    // 2. KV projection (split output) — independent of QaN path
    gemm_bf16<0, 1><<<dim3(8, 32), 256, GT_SMEM>>>(memh, meml, wh + WOFF_IN + 512 * 512,
                                                   wl + WOFF_IN + 512 * 512, in_b + 512,
                                                   nullptr, kvh, kvl, S_ * B_, 1024, 512);
    // 3. QaN block + LN1
    prep_q_kernel<<<NQ_ * H_, 32>>>(queries);
    qa_kernel<<<B_ * NW, 256, QA_SMEM>>>(tgt, wk);
    add_ln_kernel<<<MR, 256>>>(tgt, qa, ln1g, ln1b, x1, x1h, x1l, 1);
    // 4. Q projection (split output) — 6th launch: ncu capture target
    gemm_bf16<0, 1><<<dim3(4, 128), 256, GT_SMEM>>>(x1h, x1l, wh + WOFF_IN, wl + WOFF_IN,
                                                    in_b, nullptr, qh, ql, MR, 512, 512);
    // 5. attention (full HMMA)
    attn2_kernel<<<dim3(T_ / 64, H_, B_), 256, ATTN2_SMEM>>>(qh, ql, kvh, kvl, obh, obl);
    // 6. out proj + LN2
    gemm_bf16<0, 0><<<dim3(4, 128), 256, GT_SMEM>>>(obh, obl, wh + WOFF_OUT, wl + WOFF_OUT,
                                                    out_b, tmp, nullptr, nullptr, MR, 512, 512);
    add_ln_kernel<<<MR, 256>>>(x1, tmp, ln2g, ln2b, x2, x2h, x2l, 0);
    // 7. FFN + LN3
    gemm_bf16<1, 1><<<dim3(16, 128), 256, GT_SMEM>>>(x2h, x2l, wh + WOFF_L1, wl + WOFF_L1,
                                                     l1b, nullptr, hh, hl, MR, DFF_, 512);
    gemm_bf16<0, 0><<<dim3(4, 128), 256, GT_SMEM>>>(hh, hl, wh + WOFF_L2, wl + WOFF_L2,
                                                    l2b, tmp, nullptr, nullptr, MR, 512, DFF_);
    add_ln_kernel<<<MR, 256>>>(x2, tmp, ln3g, ln3b, out, nullptr, nullptr, 0);
}

// round 7
// speedup vs baseline: 1.3945x; 1.1076x over previous
#include <cuda_runtime.h>
#include <cuda_bf16.h>
#include <math.h>
#include <stdint.h>

#define T_   2048
#define B_   8
#define S_   512
#define D_   512
#define H_   8
#define DH   64
#define DFF_ 2048
#define NQ_  10
#define W_   16
#define NW   128
#define EPS  1e-5f
#define NEGV -1e30f

// ---------------- scratch (no dynamic allocation allowed) ----------------
__device__ float g_qn[NQ_ * D_];
__device__ float g_sc[T_ * B_ * NQ_];
__device__ float g_qa[B_ * NW * D_];
__device__ float g_x1[T_ * B_ * D_];
__device__ float g_q [T_ * B_ * D_];        // reused as bf16 qh|ql
__device__ float g_kv[S_ * B_ * 2 * D_];    // reused as bf16 kvh|kvl
__device__ float g_tmp[T_ * B_ * D_];
__device__ float g_x2[T_ * B_ * D_];

__device__ __nv_bfloat16 g_x1h[T_ * B_ * D_], g_x1l[T_ * B_ * D_];
__device__ __nv_bfloat16 g_x2h[T_ * B_ * D_], g_x2l[T_ * B_ * D_];
__device__ __nv_bfloat16 g_obh[T_ * B_ * D_], g_obl[T_ * B_ * D_];
__device__ __nv_bfloat16 g_hh [T_ * B_ * DFF_], g_hl [T_ * B_ * DFF_];
__device__ __nv_bfloat16 g_memh[S_ * B_ * D_], g_meml[S_ * B_ * D_];
#define WOFF_IN  0
#define WOFF_OUT (1536 * 512)
#define WOFF_L1  (WOFF_OUT + 512 * 512)
#define WOFF_L2  (WOFF_L1 + 2048 * 512)
#define WTOT     (WOFF_L2 + 512 * 2048)
__device__ __nv_bfloat16 g_wh[WTOT], g_wl[WTOT];

// ---------------- helpers ----------------
__device__ __forceinline__ uint32_t smem_u32(const void* p) {
    uint32_t a;
    asm("{ .reg .u64 t; cvta.to.shared.u64 t, %1; cvt.u32.u64 %0, t; }" : "=r"(a) : "l"(p));
    return a;
}
__device__ __forceinline__ void split1(float a, __nv_bfloat16& h, __nv_bfloat16& l) {
    h = __float2bfloat16(a);
    l = __float2bfloat16(a - __bfloat162float(h));
}
__device__ __forceinline__ void ldsm4(uint32_t* r, uint32_t addr) {
    asm volatile("ldmatrix.sync.aligned.m8n8.x4.shared.b16 {%0,%1,%2,%3}, [%4];"
        : "=r"(r[0]), "=r"(r[1]), "=r"(r[2]), "=r"(r[3]) : "r"(addr));
}
__device__ __forceinline__ void ldsm4t(uint32_t* r, uint32_t addr) {
    asm volatile("ldmatrix.sync.aligned.m8n8.x4.trans.shared.b16 {%0,%1,%2,%3}, [%4];"
        : "=r"(r[0]), "=r"(r[1]), "=r"(r[2]), "=r"(r[3]) : "r"(addr));
}
__device__ __forceinline__ void mma_bf16(float* d, const uint32_t* a, uint32_t b0, uint32_t b1) {
    asm volatile("mma.sync.aligned.m16n8k16.row.col.f32.bf16.bf16.f32 "
        "{%0,%1,%2,%3}, {%4,%5,%6,%7}, {%8,%9}, {%0,%1,%2,%3};"
        : "+f"(d[0]), "+f"(d[1]), "+f"(d[2]), "+f"(d[3])
        : "r"(a[0]), "r"(a[1]), "r"(a[2]), "r"(a[3]), "r"(b0), "r"(b1));
}
__device__ __forceinline__ void cpa16(uint32_t d, const void* s) {
    asm volatile("cp.async.cg.shared.global [%0], [%1], 16;" :: "r"(d), "l"(s));
}
#define CP_COMMIT() asm volatile("cp.async.commit_group;")
#define CP_WAIT1()  asm volatile("cp.async.wait_group 1;")

// ---------------- fused fp32 -> bf16 hi/lo split ----------------
__device__ __forceinline__ void split4_store(float4 v, __nv_bfloat162* dh, __nv_bfloat162* dl, int j) {
    __nv_bfloat16 hx, lx, hy, ly, hz, lz, hw, lw;
    split1(v.x, hx, lx); split1(v.y, hy, ly);
    split1(v.z, hz, lz); split1(v.w, hw, lw);
    dh[2 * j]     = __nv_bfloat162(hx, hy);
    dh[2 * j + 1] = __nv_bfloat162(hz, hw);
    dl[2 * j]     = __nv_bfloat162(lx, ly);
    dl[2 * j + 1] = __nv_bfloat162(lz, lw);
}

__global__ void split_all_kernel(const float4* __restrict__ inw, const float4* __restrict__ outw,
                                 const float4* __restrict__ l1w, const float4* __restrict__ l2w,
                                 const float4* __restrict__ mem,
                                 __nv_bfloat16* __restrict__ wh, __nv_bfloat16* __restrict__ wl,
                                 __nv_bfloat16* __restrict__ memh, __nv_bfloat16* __restrict__ meml) {
    int i = blockIdx.x * 256 + threadIdx.x;
    const int n0 = 1536 * 512 / 4;
    const int n1 = n0 + 512 * 512 / 4;
    const int n2 = n1 + 2048 * 512 / 4;
    const int n3 = n2 + 512 * 2048 / 4;
    const int n4 = n3 + S_ * B_ * D_ / 4;
    if (i >= n4) return;
    const float4* src; __nv_bfloat162 *dh, *dl; int j;
    if (i < n0)      { j = i;      src = inw;  dh = (__nv_bfloat162*)(wh + WOFF_IN);  dl = (__nv_bfloat162*)(wl + WOFF_IN); }
    else if (i < n1) { j = i - n0; src = outw; dh = (__nv_bfloat162*)(wh + WOFF_OUT); dl = (__nv_bfloat162*)(wl + WOFF_OUT); }
    else if (i < n2) { j = i - n1; src = l1w;  dh = (__nv_bfloat162*)(wh + WOFF_L1);  dl = (__nv_bfloat162*)(wl + WOFF_L1); }
    else if (i < n3) { j = i - n2; src = l2w;  dh = (__nv_bfloat162*)(wh + WOFF_L2);  dl = (__nv_bfloat162*)(wl + WOFF_L2); }
    else             { j = i - n3; src = mem;  dh = (__nv_bfloat162*)memh;            dl = (__nv_bfloat162*)meml; }
    split4_store(src[j], dh, dl, j);
}

// ================= HMMA GEMM (cp.async double-buffered) =================
#define STG_ELEM (128 * 40)
#define STG_BYTE (STG_ELEM * 2)
#define GT_SMEM  (8 * STG_BYTE)

template<int RELU, int OSPLIT>
__global__ __launch_bounds__(256, 2) void gemm_bf16(
    const __nv_bfloat16* __restrict__ Ah, const __nv_bfloat16* __restrict__ Al,
    const __nv_bfloat16* __restrict__ Bh, const __nv_bfloat16* __restrict__ Bl,
    const float* __restrict__ bias, float* __restrict__ C,
    __nv_bfloat16* __restrict__ Ch, __nv_bfloat16* __restrict__ Cl,
    int M, int N, int K)
{
    extern __shared__ __nv_bfloat16 dsm[];
    __nv_bfloat16* sAh = dsm;
    __nv_bfloat16* sAl = dsm + 2 * STG_ELEM;
    __nv_bfloat16* sBh = dsm + 4 * STG_ELEM;
    __nv_bfloat16* sBl = dsm + 6 * STG_ELEM;

    int tid = threadIdx.x, lane = tid & 31, wid = tid >> 5;
    int m0 = blockIdx.y * 128, n0 = blockIdx.x * 128;
    int warp_m = wid >> 2, warp_n = wid & 3;

    float acc[4][4][4];
    #pragma unroll
    for (int i = 0; i < 4; i++)
        #pragma unroll
        for (int j = 0; j < 4; j++)
            #pragma unroll
            for (int k = 0; k < 4; k++) acc[i][j][k] = 0.f;

    uint32_t uAh = smem_u32(sAh), uAl = smem_u32(sAl);
    uint32_t uBh = smem_u32(sBh), uBl = smem_u32(sBl);

    uint32_t a_off = ((warp_m * 64 + (lane & 15)) * 40 + (lane >> 4) * 8) * 2;
    uint32_t b_off = ((warp_n * 32 + ((lane >> 4) & 1) * 8 + (lane & 7)) * 40
                      + ((lane >> 3) & 1) * 8) * 2;

    int lrow = tid >> 1;
    int lp   = (tid & 1) * 16;
    uint32_t sdst = (lrow * 40 + lp) * 2;
    const __nv_bfloat16* Arow  = Ah + (size_t)(m0 + lrow) * K + lp;
    const __nv_bfloat16* Alrow = Al + (size_t)(m0 + lrow) * K + lp;
    const __nv_bfloat16* Brow  = Bh + (size_t)(n0 + lrow) * K + lp;
    const __nv_bfloat16* Blrow = Bl + (size_t)(n0 + lrow) * K + lp;

    auto prefetch = [&](int kc, int st) {
        uint32_t so = st * STG_BYTE + sdst;
        cpa16(uAh + so,      Arow + kc);
        cpa16(uAh + so + 16, Arow + kc + 8);
        cpa16(uAl + so,      Alrow + kc);
        cpa16(uAl + so + 16, Alrow + kc + 8);
        cpa16(uBh + so,      Brow + kc);
        cpa16(uBh + so + 16, Brow + kc + 8);
        cpa16(uBl + so,      Blrow + kc);
        cpa16(uBl + so + 16, Blrow + kc + 8);
        CP_COMMIT();
    };

    int nch = K >> 5;
    prefetch(0, 0);
    prefetch(32, 1);

    for (int c = 0; c < nch; c++) {
        CP_WAIT1();
        __syncthreads();
        uint32_t stb = (c & 1) * STG_BYTE;
        #pragma unroll
        for (int ks = 0; ks < 2; ks++) {
            uint32_t bh0[4], bh1[4], bl0[4], bl1[4];
            ldsm4(bh0, uBh + stb + b_off + ks * 32);
            ldsm4(bh1, uBh + stb + b_off + 1280 + ks * 32);
            ldsm4(bl0, uBl + stb + b_off + ks * 32);
            ldsm4(bl1, uBl + stb + b_off + 1280 + ks * 32);
            #pragma unroll
            for (int mi = 0; mi < 4; mi++) {
                uint32_t ah[4], al[4];
                ldsm4(ah, uAh + stb + a_off + mi * 1280 + ks * 32);
                ldsm4(al, uAl + stb + a_off + mi * 1280 + ks * 32);
                mma_bf16(acc[mi][0], ah, bh0[0], bh0[1]);
                mma_bf16(acc[mi][1], ah, bh0[2], bh0[3]);
                mma_bf16(acc[mi][2], ah, bh1[0], bh1[1]);
                mma_bf16(acc[mi][3], ah, bh1[2], bh1[3]);
                mma_bf16(acc[mi][0], ah, bl0[0], bl0[1]);
                mma_bf16(acc[mi][1], ah, bl0[2], bl0[3]);
                mma_bf16(acc[mi][2], ah, bl1[0], bl1[1]);
                mma_bf16(acc[mi][3], ah, bl1[2], bl1[3]);
                mma_bf16(acc[mi][0], al, bh0[0], bh0[1]);
                mma_bf16(acc[mi][1], al, bh0[2], bh0[3]);
                mma_bf16(acc[mi][2], al, bh1[0], bh1[1]);
                mma_bf16(acc[mi][3], al, bh1[2], bh1[3]);
            }
        }
        __syncthreads();
        int nk = c + 2;
        if (nk < nch) prefetch(nk << 5, nk & 1);
    }

    int r0 = lane >> 2, c0 = (lane & 3) * 2;
    int mbase = m0 + warp_m * 64, nbase = n0 + warp_n * 32;
    #pragma unroll
    for (int mi = 0; mi < 4; mi++) {
        #pragma unroll
        for (int nj = 0; nj < 4; nj++) {
            int nn = nbase + nj * 8 + c0;
            float b0 = bias[nn], b1 = bias[nn + 1];
            #pragma unroll
            for (int half = 0; half < 2; half++) {
                int mm = mbase + mi * 16 + r0 + half * 8;
                float v0 = acc[mi][nj][half * 2]     + b0;
                float v1 = acc[mi][nj][half * 2 + 1] + b1;
                if (RELU) { v0 = fmaxf(v0, 0.f); v1 = fmaxf(v1, 0.f); }
                size_t off = (size_t)mm * N + nn;
                if (OSPLIT) {
                    __nv_bfloat16 h0, l0, h1, l1;
                    split1(v0, h0, l0); split1(v1, h1, l1);
                    *(__nv_bfloat162*)(Ch + off) = __nv_bfloat162(h0, h1);
                    *(__nv_bfloat162*)(Cl + off) = __nv_bfloat162(l0, l1);
                } else {
                    *(float2*)(C + off) = make_float2(v0, v1);
                }
            }
        }
    }
}

// ---------------- query normalization (QaN) ----------------
__global__ void prep_q_kernel(const float* __restrict__ q) {
    int n = blockIdx.x / H_, h = blockIdx.x % H_;
    int lane = threadIdx.x;
    const float* base = q + n * D_ + h * DH;
    float v0 = base[lane];
    float v1 = base[lane + 32];
    float ss = v0 * v0 + v1 * v1;
    #pragma unroll
    for (int o = 16; o; o >>= 1) ss += __shfl_xor_sync(0xffffffffu, ss, o);
    float f = 1.0f / ((sqrtf(ss) + 1e-6f) * 8.0f * sqrtf(512.0f));
    g_qn[n * D_ + h * DH + lane]      = v0 * f;
    g_qn[n * D_ + h * DH + lane + 32] = v1 * f;
}

// ---------------- QaN scores: s[t,b,n] = qn[n] . tgt[t,b,:] ----------------
__global__ __launch_bounds__(256) void qa_score_kernel(const float* __restrict__ tgt) {
    __shared__ float qs[NQ_ * D_];
    int tid = threadIdx.x, lane = tid & 31, wid = tid >> 5;
    for (int i = tid; i < NQ_ * D_; i += 256) qs[i] = g_qn[i];
    __syncthreads();

    int r = blockIdx.x * 8 + wid;   // row = t*B + b
    const float* row = tgt + (size_t)r * D_;
    float x[16];
    #pragma unroll
    for (int i = 0; i < 4; i++) {
        float4 v = *(const float4*)(row + i * 128 + lane * 4);
        x[i * 4] = v.x; x[i * 4 + 1] = v.y; x[i * 4 + 2] = v.z; x[i * 4 + 3] = v.w;
    }
    #pragma unroll
    for (int n = 0; n < NQ_; n++) {
        const float* qr = qs + n * D_;
        float s = 0.f;
        #pragma unroll
        for (int i = 0; i < 4; i++) {
            s += x[i * 4]     * qr[i * 128 + lane * 4];
            s += x[i * 4 + 1] * qr[i * 128 + lane * 4 + 1];
            s += x[i * 4 + 2] * qr[i * 128 + lane * 4 + 2];
            s += x[i * 4 + 3] * qr[i * 128 + lane * 4 + 3];
        }
        #pragma unroll
        for (int o = 16; o; o >>= 1) s += __shfl_xor_sync(0xffffffffu, s, o);
        if (lane == 0) g_sc[r * NQ_ + n] = s;
    }
}

// ---------------- QaN output: softmax(48) + wk mix + value sum ----------------
__global__ __launch_bounds__(256) void qa_out_kernel(const float* __restrict__ tgt,
                                                     const float* __restrict__ wk) {
    __shared__ float ssc[NQ_ * 48];
    __shared__ float swj[48];
    int bx = blockIdx.x;
    int b = bx >> 7, m = bx & 127;
    int tid = threadIdx.x, lane = tid & 31, wid = tid >> 5;
    int t0 = (m - 1) * W_;

    // load 48x10 scores with edge masking
    for (int idx = tid; idx < NQ_ * 48; idx += 256) {
        int n = idx / 48, j = idx % 48;
        int win = m - 1 + (j >> 4);
        float v = NEGV;
        if (win >= 0 && win < NW) v = g_sc[(size_t)(t0 + j) * B_ * NQ_ + b * NQ_ + n];
        ssc[n * 48 + j] = v;
    }
    __syncthreads();

    // softmax per query row n (warp per row; rows n = wid, wid+8)
    for (int n = wid; n < NQ_; n += 8) {
        float v0 = ssc[n * 48 + lane];
        float v1 = (lane < 16) ? ssc[n * 48 + 32 + lane] : NEGV;
        float mx = fmaxf(v0, v1);
        #pragma unroll
        for (int o = 16; o; o >>= 1) mx = fmaxf(mx, __shfl_xor_sync(0xffffffffu, mx, o));
        float e0 = __expf(v0 - mx);
        float e1 = (lane < 16) ? __expf(v1 - mx) : 0.f;
        float su = e0 + e1;
        #pragma unroll
        for (int o = 16; o; o >>= 1) su += __shfl_xor_sync(0xffffffffu, su, o);
        float inv = 1.0f / su;
        ssc[n * 48 + lane] = e0 * inv;
        if (lane < 16) ssc[n * 48 + 32 + lane] = e1 * inv;
    }
    __syncthreads();

    if (tid < 48) {
        float acc = 0.f;
        #pragma unroll
        for (int n = 0; n < NQ_; n++) acc += wk[n] * ssc[n * 48 + tid];
        swj[tid] = acc;
    }
    __syncthreads();

    // value sum: out[d] = sum_j wj[j] * tgt[t0+j, b, d]
    int js = (m == 0) ? 16 : 0;
    int je = (m == NW - 1) ? 32 : 48;
    float acc0 = 0.f, acc1 = 0.f;
    const float* base = tgt + ((size_t)(t0 + js) * B_ + b) * D_ + tid;
    for (int j = js; j < je; j++) {
        float w = swj[j];
        acc0 += w * base[0];
        acc1 += w * base[256];
        base += (size_t)B_ * D_;
    }
    size_t o = ((size_t)b * NW + m) * D_ + tid;
    g_qa[o]       = acc0;
    g_qa[o + 256] = acc1;
}

// ---------------- residual add + LayerNorm ----------------
__device__ __forceinline__ float block_sum(float v, float* red) {
    int lane = threadIdx.x & 31, w = threadIdx.x >> 5;
    __syncthreads();
    #pragma unroll
    for (int o = 16; o; o >>= 1) v += __shfl_xor_sync(0xffffffffu, v, o);
    if (lane == 0) red[w] = v;
    __syncthreads();
    v = (lane < 8) ? red[lane] : 0.f;
    #pragma unroll
    for (int o = 4; o; o >>= 1) v += __shfl_xor_sync(0xffffffffu, v, o);
    return __shfl_sync(0xffffffffu, v, 0);
}

__global__ __launch_bounds__(256) void add_ln_kernel(const float* __restrict__ a,
                                                     const float* __restrict__ bsrc,
                                                     const float* __restrict__ g,
                                                     const float* __restrict__ be,
                                                     float* __restrict__ out,
                                                     __nv_bfloat16* __restrict__ oh,
                                                     __nv_bfloat16* __restrict__ ol,
                                                     int mode) {
    __shared__ float red[8];
    int r = blockIdx.x, tid = threadIdx.x;
    const float* ar = a + (size_t)r * D_;
    const float* br;
    if (mode == 1) {
        int t = r / B_, b = r % B_;
        br = bsrc + (size_t)(b * NW + (t >> 4)) * D_;
    } else {
        br = bsrc + (size_t)r * D_;
    }
    float x0 = ar[tid]       + br[tid];
    float x1 = ar[tid + 256] + br[tid + 256];
    float mu = block_sum(x0 + x1, red) * (1.0f / 512.0f);
    float d0 = x0 - mu, d1 = x1 - mu;
    float var = block_sum(d0 * d0 + d1 * d1, red) * (1.0f / 512.0f);
    float inv = rsqrtf(var + EPS);
    float y0 = d0 * inv * g[tid]       + be[tid];
    float y1 = d1 * inv * g[tid + 256] + be[tid + 256];
    size_t o0 = (size_t)r * D_ + tid, o1 = o0 + 256;
    out[o0] = y0;
    out[o1] = y1;
    if (oh) {
        __nv_bfloat16 h, l;
        split1(y0, h, l); oh[o0] = h; ol[o0] = l;
        split1(y1, h, l); oh[o1] = h; ol[o1] = l;
    }
}

// ---------------- cross attention v2: full HMMA (split bf16) ----------------
#define SROW2  524
#define SROWB  (SROW2 * 4)
#define AT_QH  (64 * SROW2 * 4)
#define AT_QL  (AT_QH + 64 * 72 * 2)
#define AT_KH  (AT_QL + 64 * 72 * 2)
#define AT_KL  (AT_KH + 128 * 72 * 2)
#define ATTN2_SMEM (AT_KL + 128 * 72 * 2)

__global__ __launch_bounds__(256, 1) void attn2_kernel(
    const __nv_bfloat16* __restrict__ Qh, const __nv_bfloat16* __restrict__ Ql,
    const __nv_bfloat16* __restrict__ KVh, const __nv_bfloat16* __restrict__ KVl,
    __nv_bfloat16* __restrict__ Oh, __nv_bfloat16* __restrict__ Ol)
{
    extern __shared__ char smc[];
    float* Ss = (float*)smc;
    uint32_t uS  = smem_u32(smc);
    uint32_t uQh = uS + AT_QH, uQl = uS + AT_QL;
    uint32_t uKh = uS + AT_KH, uKl = uS + AT_KL;

    int qt0 = blockIdx.x * 64, h = blockIdx.y, b = blockIdx.z;
    int tid = threadIdx.x, lane = tid & 31, wid = tid >> 5;
    int r0 = lane >> 2, c0 = (lane & 3) * 2;

    auto loadKV = [&](int sch, int col) {
        for (int idx = tid; idx < 1024; idx += 256) {
            int s = idx >> 3, dg = (idx & 7) * 8;
            size_t go = ((size_t)(sch + s) * B_ + b) * 1024 + col + h * DH + dg;
            *(uint4*)(smc + AT_KH + (s * 72 + dg) * 2) = *(const uint4*)(KVh + go);
            *(uint4*)(smc + AT_KL + (s * 72 + dg) * 2) = *(const uint4*)(KVl + go);
        }
    };

    {
        __nv_bfloat162 sc = __floats2bfloat162_rn(0.125f, 0.125f);
        for (int idx = tid; idx < 64 * 32; idx += 256) {
            int i = idx >> 5, dp = idx & 31;
            size_t go = (((size_t)(qt0 + i) * B_ + b) * D_ + h * DH) / 2 + dp;
            __nv_bfloat162 vh = ((const __nv_bfloat162*)Qh)[go];
            __nv_bfloat162 vl = ((const __nv_bfloat162*)Ql)[go];
            ((__nv_bfloat162*)(smc + AT_QH))[i * 36 + dp] = __hmul2(vh, sc);
            ((__nv_bfloat162*)(smc + AT_QL))[i * 36 + dp] = __hmul2(vl, sc);
        }
    }
    loadKV(0, 0);
    __syncthreads();

    int wq = wid >> 2, ws = wid & 3;
    uint32_t a_lo = ((lane & 15) * 72 + (lane >> 4) * 8) * 2;
    uint32_t b_lo = ((((lane >> 4) & 1) * 8 + (lane & 7)) * 72 + ((lane >> 3) & 1) * 8) * 2;

    uint32_t aqh[2][4][4], aql[2][4][4];
    #pragma unroll
    for (int mi = 0; mi < 2; mi++)
        #pragma unroll
        for (int ks = 0; ks < 4; ks++) {
            ldsm4(aqh[mi][ks], uQh + (wq * 32 + mi * 16) * 144 + a_lo + ks * 32);
            ldsm4(aql[mi][ks], uQl + (wq * 32 + mi * 16) * 144 + a_lo + ks * 32);
        }

    for (int c = 0; c < 4; c++) {
        int sch = c * 128;
        float acc[2][4][4];
        #pragma unroll
        for (int i = 0; i < 2; i++)
            #pragma unroll
            for (int j = 0; j < 4; j++)
                #pragma unroll
                for (int k = 0; k < 4; k++) acc[i][j][k] = 0.f;

        #pragma unroll
        for (int ks = 0; ks < 4; ks++) {
            uint32_t kh0[4], kh1[4], kl0[4], kl1[4];
            uint32_t kb = uKh + (ws * 32) * 144 + b_lo + ks * 32;
            ldsm4(kh0, kb);
            ldsm4(kh1, kb + 16 * 144);
            uint32_t klb = uKl + (ws * 32) * 144 + b_lo + ks * 32;
            ldsm4(kl0, klb);
            ldsm4(kl1, klb + 16 * 144);
            #pragma unroll
            for (int mi = 0; mi < 2; mi++) {
                mma_bf16(acc[mi][0], aqh[mi][ks], kh0[0], kh0[1]);
                mma_bf16(acc[mi][1], aqh[mi][ks], kh0[2], kh0[3]);
                mma_bf16(acc[mi][2], aqh[mi][ks], kh1[0], kh1[1]);
                mma_bf16(acc[mi][3], aqh[mi][ks], kh1[2], kh1[3]);
                mma_bf16(acc[mi][0], aqh[mi][ks], kl0[0], kl0[1]);
                mma_bf16(acc[mi][1], aqh[mi][ks], kl0[2], kl0[3]);
                mma_bf16(acc[mi][2], aqh[mi][ks], kl1[0], kl1[1]);
                mma_bf16(acc[mi][3], aqh[mi][ks], kl1[2], kl1[3]);
                mma_bf16(acc[mi][0], aql[mi][ks], kh0[0], kh0[1]);
                mma_bf16(acc[mi][1], aql[mi][ks], kh0[2], kh0[3]);
                mma_bf16(acc[mi][2], aql[mi][ks], kh1[0], kh1[1]);
                mma_bf16(acc[mi][3], aql[mi][ks], kh1[2], kh1[3]);
            }
        }
        #pragma unroll
        for (int mi = 0; mi < 2; mi++)
            #pragma unroll
            for (int nj = 0; nj < 4; nj++)
                #pragma unroll
                for (int half = 0; half < 2; half++) {
                    int qr = wq * 32 + mi * 16 + r0 + half * 8;
                    int scol = sch + ws * 32 + nj * 8 + c0;
                    *(float2*)&Ss[qr * SROW2 + scol] =
                        make_float2(acc[mi][nj][half * 2], acc[mi][nj][half * 2 + 1]);
                }
        __syncthreads();
        if (c < 3) { loadKV(sch + 128, 0); __syncthreads(); }
    }

    {
        int i0 = wid * 8;
        for (int i = i0; i < i0 + 8; i++) {
            float* row = Ss + i * SROW2;
            float v[16];
            #pragma unroll
            for (int j = 0; j < 16; j++) v[j] = row[lane + 32 * j];
            float mx = v[0];
            #pragma unroll
            for (int j = 1; j < 16; j++) mx = fmaxf(mx, v[j]);
            #pragma unroll
            for (int o = 16; o; o >>= 1) mx = fmaxf(mx, __shfl_xor_sync(0xffffffffu, mx, o));
            float su = 0.f;
            #pragma unroll
            for (int j = 0; j < 16; j++) { v[j] = __expf(v[j] - mx); su += v[j]; }
            #pragma unroll
            for (int o = 16; o; o >>= 1) su += __shfl_xor_sync(0xffffffffu, su, o);
            float inv = 1.0f / su;
            __syncwarp();
            __nv_bfloat16* rh = (__nv_bfloat16*)row;
            __nv_bfloat16* rl = rh + 512;
            #pragma unroll
            for (int j = 0; j < 16; j++) {
                __nv_bfloat16 hh, ll;
                split1(v[j] * inv, hh, ll);
                rh[lane + 32 * j] = hh;
                rl[lane + 32 * j] = ll;
            }
        }
    }
    __syncthreads();

    int wq2 = wid >> 1, wd = wid & 1;
    float oacc[4][4];
    #pragma unroll
    for (int j = 0; j < 4; j++)
        #pragma unroll
        for (int k = 0; k < 4; k++) oacc[j][k] = 0.f;

    uint32_t pa = uS + (wq2 * 16 + (lane & 15)) * SROWB + (lane >> 4) * 16;
    uint32_t vb_lo = ((lane & 15) * 72 + (wd * 32 + (lane >> 4) * 8)) * 2;

    for (int c = 0; c < 4; c++) {
        loadKV(c * 128, 512);
        __syncthreads();
        #pragma unroll
        for (int ks = 0; ks < 8; ks++) {
            uint32_t ph[4], pl[4];
            uint32_t paddr = pa + (c * 128 + ks * 16) * 2;
            ldsm4(ph, paddr);
            ldsm4(pl, paddr + 1024);
            uint32_t vh0[4], vh1[4], vl0[4], vl1[4];
            uint32_t va = uKh + vb_lo + ks * 16 * 144;
            ldsm4t(vh0, va);
            ldsm4t(vh1, va + 32);
            uint32_t vla = uKl + vb_lo + ks * 16 * 144;
            ldsm4t(vl0, vla);
            ldsm4t(vl1, vla + 32);
            mma_bf16(oacc[0], ph, vh0[0], vh0[1]);
            mma_bf16(oacc[1], ph, vh0[2], vh0[3]);
            mma_bf16(oacc[2], ph, vh1[0], vh1[1]);
            mma_bf16(oacc[3], ph, vh1[2], vh1[3]);
            mma_bf16(oacc[0], ph, vl0[0], vl0[1]);
            mma_bf16(oacc[1], ph, vl0[2], vl0[3]);
            mma_bf16(oacc[2], ph, vl1[0], vl1[1]);
            mma_bf16(oacc[3], ph, vl1[2], vl1[3]);
            mma_bf16(oacc[0], pl, vh0[0], vh0[1]);
            mma_bf16(oacc[1], pl, vh0[2], vh0[3]);
            mma_bf16(oacc[2], pl, vh1[0], vh1[1]);
            mma_bf16(oacc[3], pl, vh1[2], vh1[3]);
        }
        __syncthreads();
    }

    #pragma unroll
    for (int nj = 0; nj < 4; nj++)
        #pragma unroll
        for (int half = 0; half < 2; half++) {
            int q = qt0 + wq2 * 16 + r0 + half * 8;
            int d = wd * 32 + nj * 8 + c0;
            size_t off = ((size_t)q * B_ + b) * D_ + h * DH + d;
            __nv_bfloat16 h0, l0, h1, l1;
            split1(oacc[nj][half * 2], h0, l0);
            split1(oacc[nj][half * 2 + 1], h1, l1);
            *(__nv_bfloat162*)(Oh + off) = __nv_bfloat162(h0, h1);
            *(__nv_bfloat162*)(Ol + off) = __nv_bfloat162(l0, l1);
        }
}

// ---------------- host launcher ----------------
extern "C" void kernel_launch(void* const* d_in, const int* in_sizes, int n_in,
                              void* d_out, int out_size) {
    const float* tgt     = (const float*)d_in[0];
    const float* memory  = (const float*)d_in[1];
    const float* queries = (const float*)d_in[2];
    const float* wk      = (const float*)d_in[3];
    const float* in_w    = (const float*)d_in[4];
    const float* in_b    = (const float*)d_in[5];
    const float* out_w   = (const float*)d_in[6];
    const float* out_b   = (const float*)d_in[7];
    const float* l1w     = (const float*)d_in[8];
    const float* l1b     = (const float*)d_in[9];
    const float* l2w     = (const float*)d_in[10];
    const float* l2b     = (const float*)d_in[11];
    const float* ln1g    = (const float*)d_in[12];
    const float* ln1b    = (const float*)d_in[13];
    const float* ln2g    = (const float*)d_in[14];
    const float* ln2b    = (const float*)d_in[15];
    const float* ln3g    = (const float*)d_in[16];
    const float* ln3b    = (const float*)d_in[17];
    float* out = (float*)d_out;

    float *qa, *x1, *qb, *kv, *tmp, *x2;
    __nv_bfloat16 *x1h, *x1l, *x2h, *x2l, *obh, *obl, *hh, *hl, *memh, *meml, *wh, *wl;
    cudaGetSymbolAddress((void**)&qa,  g_qa);
    cudaGetSymbolAddress((void**)&x1,  g_x1);
    cudaGetSymbolAddress((void**)&qb,  g_q);
    cudaGetSymbolAddress((void**)&kv,  g_kv);
    cudaGetSymbolAddress((void**)&tmp, g_tmp);
    cudaGetSymbolAddress((void**)&x2,  g_x2);
    cudaGetSymbolAddress((void**)&x1h, g_x1h); cudaGetSymbolAddress((void**)&x1l, g_x1l);
    cudaGetSymbolAddress((void**)&x2h, g_x2h); cudaGetSymbolAddress((void**)&x2l, g_x2l);
    cudaGetSymbolAddress((void**)&obh, g_obh); cudaGetSymbolAddress((void**)&obl, g_obl);
    cudaGetSymbolAddress((void**)&hh,  g_hh);  cudaGetSymbolAddress((void**)&hl,  g_hl);
    cudaGetSymbolAddress((void**)&memh, g_memh); cudaGetSymbolAddress((void**)&meml, g_meml);
    cudaGetSymbolAddress((void**)&wh,  g_wh);  cudaGetSymbolAddress((void**)&wl,  g_wl);

    __nv_bfloat16* qh  = (__nv_bfloat16*)qb;
    __nv_bfloat16* ql  = qh + (size_t)T_ * B_ * D_;
    __nv_bfloat16* kvh = (__nv_bfloat16*)kv;
    __nv_bfloat16* kvl = kvh + (size_t)S_ * B_ * 2 * D_;

    cudaFuncSetAttribute(attn2_kernel, cudaFuncAttributeMaxDynamicSharedMemorySize, ATTN2_SMEM);
    cudaFuncSetAttribute(gemm_bf16<0,0>, cudaFuncAttributeMaxDynamicSharedMemorySize, GT_SMEM);
    cudaFuncSetAttribute(gemm_bf16<0,1>, cudaFuncAttributeMaxDynamicSharedMemorySize, GT_SMEM);
    cudaFuncSetAttribute(gemm_bf16<1,1>, cudaFuncAttributeMaxDynamicSharedMemorySize, GT_SMEM);

    const int MR = T_ * B_;

    // 1. fused split of all weights + memory
    split_all_kernel<<<5120, 256>>>((const float4*)in_w, (const float4*)out_w,
                                    (const float4*)l1w, (const float4*)l2w,
                                    (const float4*)memory, wh, wl, memh, meml);
    // 2. KV projection (split output)
    gemm_bf16<0, 1><<<dim3(8, 32), 256, GT_SMEM>>>(memh, meml, wh + WOFF_IN + 512 * 512,
                                                   wl + WOFF_IN + 512 * 512, in_b + 512,
                                                   nullptr, kvh, kvl, S_ * B_, 1024, 512);
    // 3. QaN block + LN1 (restructured: score pass + output pass)
    prep_q_kernel<<<NQ_ * H_, 32>>>(queries);
    qa_score_kernel<<<MR / 8, 256>>>(tgt);
    qa_out_kernel<<<B_ * NW, 256>>>(tgt, wk);
    add_ln_kernel<<<MR, 256>>>(tgt, qa, ln1g, ln1b, x1, x1h, x1l, 1);
    // 4. Q projection (split output)
    gemm_bf16<0, 1><<<dim3(4, 128), 256, GT_SMEM>>>(x1h, x1l, wh + WOFF_IN, wl + WOFF_IN,
                                                    in_b, nullptr, qh, ql, MR, 512, 512);
    // 5. attention (full HMMA)
    attn2_kernel<<<dim3(T_ / 64, H_, B_), 256, ATTN2_SMEM>>>(qh, ql, kvh, kvl, obh, obl);
    // 6. out proj + LN2
    gemm_bf16<0, 0><<<dim3(4, 128), 256, GT_SMEM>>>(obh, obl, wh + WOFF_OUT, wl + WOFF_OUT,
                                                    out_b, tmp, nullptr, nullptr, MR, 512, 512);
    add_ln_kernel<<<MR, 256>>>(x1, tmp, ln2g, ln2b, x2, x2h, x2l, 0);
    // 7. FFN + LN3
    gemm_bf16<1, 1><<<dim3(16, 128), 256, GT_SMEM>>>(x2h, x2l, wh + WOFF_L1, wl + WOFF_L1,
                                                     l1b, nullptr, hh, hl, MR, DFF_, 512);
    gemm_bf16<0, 0><<<dim3(4, 128), 256, GT_SMEM>>>(hh, hl, wh + WOFF_L2, wl + WOFF_L2,
                                                    l2b, tmp, nullptr, nullptr, MR, 512, DFF_);
    add_ln_kernel<<<MR, 256>>>(x2, tmp, ln3g, ln3b, out, nullptr, nullptr, 0);
}